// round 2
// baseline (speedup 1.0000x reference)
#include <cuda_runtime.h>
#include <cuda_bf16.h>

// Problem constants: B=4, C=512, CI=128, H=W=64, N=4096
#define PB  4
#define PC  512
#define PCI 128
#define PN  4096

// Scratch (no allocations allowed -> __device__ globals)
__device__ float g_q[(size_t)PB * PCI * PN];             // 8 MB
__device__ float g_k[(size_t)PB * PCI * PN];             // 8 MB
__device__ float g_v[(size_t)PB * PCI * PN];             // 8 MB
__device__ float g_e[(size_t)PB * PN * PN];              // 268 MB (energy -> attn in place)
__device__ float g_o[(size_t)PB * PCI * PN];             // 8 MB

// ----------------------------------------------------------------------------
// Generic batched tiled SGEMM:
//   C[z][m][n] = sum_k A[z](m,k) * B[z](k,n)  (+ bias[m]) (+ res[z][m][n])
// A addressed as A[z*a_sb + m*a_sm + k*a_sk], B as B[z*b_sb + k*b_sk + n*b_sn].
// AKC: A contiguous along k (a_sk==1) -> load order chosen for coalescing.
// BNC: B contiguous along n (b_sn==1).
// Tiles: TM x TN x 16, 256 threads, (TM/16)x(TN/16) per-thread register tile.
// All dims divide tiles exactly for this problem -> no bounds checks.
// ----------------------------------------------------------------------------
template<int TM, int TN, bool AKC, bool BNC>
__global__ void __launch_bounds__(256)
gemm_tile(const float* __restrict__ A, long long a_sm, long long a_sk, long long a_sb,
          const float* __restrict__ B, long long b_sk, long long b_sn, long long b_sb,
          float* __restrict__ C, long long c_sm, long long c_sb,
          const float* __restrict__ bias,
          const float* __restrict__ res, long long r_sb,
          int K)
{
    constexpr int TK = 16;
    constexpr int RM = TM / 16;
    constexpr int RN = TN / 16;
    constexpr int A_PT = (TK * TM) / 256;
    constexpr int B_PT = (TK * TN) / 256;

    __shared__ float As[TK][TM + 4];
    __shared__ float Bs[TK][TN + 4];

    const int tid = threadIdx.x;
    const int tx  = tid & 15;
    const int ty  = tid >> 4;
    const int m0  = blockIdx.y * TM;
    const int n0  = blockIdx.x * TN;

    const float* Ab = A + (long long)blockIdx.z * a_sb + (long long)m0 * a_sm;
    const float* Bb = B + (long long)blockIdx.z * b_sb + (long long)n0 * b_sn;

    float acc[RM][RN];
#pragma unroll
    for (int i = 0; i < RM; i++)
#pragma unroll
        for (int j = 0; j < RN; j++) acc[i][j] = 0.0f;

    for (int kt = 0; kt < K; kt += TK) {
        // ---- load A tile ----
#pragma unroll
        for (int i = 0; i < A_PT; i++) {
            int idx = tid + i * 256;
            int m, k;
            if (AKC) { m = idx / TK; k = idx % TK; }   // consecutive tid -> consecutive k (stride 1)
            else     { k = idx / TM; m = idx % TM; }   // consecutive tid -> consecutive m (stride 1)
            As[k][m] = __ldg(&Ab[(long long)m * a_sm + (long long)(kt + k) * a_sk]);
        }
        // ---- load B tile ----
#pragma unroll
        for (int i = 0; i < B_PT; i++) {
            int idx = tid + i * 256;
            int n, k;
            if (BNC) { k = idx / TN; n = idx % TN; }   // consecutive tid -> consecutive n (stride 1)
            else     { n = idx / TK; k = idx % TK; }   // consecutive tid -> consecutive k (stride 1)
            Bs[k][n] = __ldg(&Bb[(long long)(kt + k) * b_sk + (long long)n * b_sn]);
        }
        __syncthreads();

#pragma unroll
        for (int kk = 0; kk < TK; kk++) {
            float a[RM], b[RN];
#pragma unroll
            for (int i = 0; i < RM; i++) a[i] = As[kk][ty * RM + i];
#pragma unroll
            for (int j = 0; j < RN; j++) b[j] = Bs[kk][tx * RN + j];
#pragma unroll
            for (int i = 0; i < RM; i++)
#pragma unroll
                for (int j = 0; j < RN; j++)
                    acc[i][j] += a[i] * b[j];
        }
        __syncthreads();
    }

    // ---- epilogue ----
    float* Cb = C + (long long)blockIdx.z * c_sb;
    const float* Rb = res ? res + (long long)blockIdx.z * r_sb : nullptr;
#pragma unroll
    for (int i = 0; i < RM; i++) {
        const int m = m0 + ty * RM + i;
        const float bv = bias ? bias[m] : 0.0f;
#pragma unroll
        for (int j = 0; j < RN; j++) {
            const int n = n0 + tx * RN + j;
            const long long off = (long long)m * c_sm + n;
            float vvv = acc[i][j] + bv;
            if (Rb) vvv += Rb[off];
            Cb[off] = vvv;
        }
    }
}

// ----------------------------------------------------------------------------
// Row softmax over rows of length 4096 (one block per row, 16 elems/thread).
// Matches jax.nn.softmax (max-subtracted).
// ----------------------------------------------------------------------------
__global__ void __launch_bounds__(256) softmax4096(float* __restrict__ e)
{
    constexpr int N = PN;
    constexpr int PT = N / 256; // 16
    float* p = e + (size_t)blockIdx.x * N;
    const int tid = threadIdx.x;

    float v[PT];
    float mx = -1e30f;
#pragma unroll
    for (int i = 0; i < PT; i++) {
        v[i] = p[tid + i * 256];
        mx = fmaxf(mx, v[i]);
    }

    __shared__ float red[256];
    red[tid] = mx;
    __syncthreads();
#pragma unroll
    for (int s = 128; s > 0; s >>= 1) {
        if (tid < s) red[tid] = fmaxf(red[tid], red[tid + s]);
        __syncthreads();
    }
    mx = red[0];
    __syncthreads();

    float sum = 0.0f;
#pragma unroll
    for (int i = 0; i < PT; i++) {
        v[i] = __expf(v[i] - mx);
        sum += v[i];
    }
    red[tid] = sum;
    __syncthreads();
#pragma unroll
    for (int s = 128; s > 0; s >>= 1) {
        if (tid < s) red[tid] += red[tid + s];
        __syncthreads();
    }
    const float inv = 1.0f / red[0];
#pragma unroll
    for (int i = 0; i < PT; i++) p[tid + i * 256] = v[i] * inv;
}

// ----------------------------------------------------------------------------
// Launch
// ----------------------------------------------------------------------------
extern "C" void kernel_launch(void* const* d_in, const int* in_sizes, int n_in,
                              void* d_out, int out_size)
{
    (void)in_sizes; (void)n_in; (void)out_size;
    const float* x  = (const float*)d_in[0];
    const float* wq = (const float*)d_in[1];
    const float* bq = (const float*)d_in[2];
    const float* wk = (const float*)d_in[3];
    const float* bk = (const float*)d_in[4];
    const float* wv = (const float*)d_in[5];
    const float* bv = (const float*)d_in[6];
    const float* wo = (const float*)d_in[7];
    const float* bo = (const float*)d_in[8];
    float* out = (float*)d_out;

    static float *q = nullptr, *k = nullptr, *v = nullptr, *e = nullptr, *o = nullptr;
    if (!q) {
        cudaGetSymbolAddress((void**)&q, g_q);
        cudaGetSymbolAddress((void**)&k, g_k);
        cudaGetSymbolAddress((void**)&v, g_v);
        cudaGetSymbolAddress((void**)&e, g_e);
        cudaGetSymbolAddress((void**)&o, g_o);
    }

    const long long N = PN, C = PC, CI = PCI;
    const long long xsb  = C * N;        // x batch stride
    const long long qsb  = CI * N;       // q/k/v/o batch stride
    const long long esb  = N * N;        // energy batch stride
    dim3 blk(256);

    // 1) q/k/v projections: [CI,C] x [C,N] + bias   (A=weight AKC, B=x BNC)
    gemm_tile<128,128,true,true><<<dim3(PN/128, PCI/128, PB), blk>>>(
        wq, C, 1, 0,  x, N, 1, xsb,  q, N, qsb,  bq, nullptr, 0, (int)C);
    gemm_tile<128,128,true,true><<<dim3(PN/128, PCI/128, PB), blk>>>(
        wk, C, 1, 0,  x, N, 1, xsb,  k, N, qsb,  bk, nullptr, 0, (int)C);
    gemm_tile<128,128,true,true><<<dim3(PN/128, PCI/128, PB), blk>>>(
        wv, C, 1, 0,  x, N, 1, xsb,  v, N, qsb,  bv, nullptr, 0, (int)C);

    // 2) energy[i,j] = sum_c q[c,i] k[c,j]   (A = q^T: m-contig; B = k: n-contig)
    gemm_tile<128,128,false,true><<<dim3(PN/128, PN/128, PB), blk>>>(
        q, 1, N, qsb,  k, N, 1, qsb,  e, N, esb,  nullptr, nullptr, 0, (int)CI);

    // 3) softmax over rows (in place)
    softmax4096<<<PB * PN, blk>>>(e);

    // 4) o[c,i] = sum_j v[c,j] attn[i,j]   (A = v: k-contig; B = attn^T: k-contig)
    gemm_tile<64,128,true,false><<<dim3(PN/128, PCI/64, PB), blk>>>(
        v, N, 1, qsb,  e, 1, N, esb,  o, N, qsb,  nullptr, nullptr, 0, (int)N);

    // 5) out = wo * o + bo + x (residual)
    gemm_tile<128,128,true,true><<<dim3(PN/128, PC/128, PB), blk>>>(
        wo, CI, 1, 0,  o, N, 1, qsb,  out, N, xsb,  bo, x, xsb, (int)CI);
}

// round 5
// speedup vs baseline: 2.0337x; 2.0337x over previous
#include <cuda_runtime.h>
#include <cuda_bf16.h>
#include <cstdint>

// Problem constants: B=4, C=512, CI=128, H=W=64, N=4096
#define PB  4
#define PC  512
#define PCI 128
#define PN  4096

typedef __nv_bfloat16 bf16;

// ---------------- scratch (no allocations allowed -> __device__ globals) ---
// Total ~316 MB (vs 592 MB in the twice-failed round — footprint hypothesis test)
__device__ float g_q[(size_t)PB * PCI * PN];            // [b][c][n] fp32   8 MB
__device__ float g_k[(size_t)PB * PCI * PN];            //                  8 MB
__device__ float g_v[(size_t)PB * PCI * PN];            //                  8 MB
__device__ float g_e[(size_t)PB * PN * PN];             // 268 MB: energy fp32 [b][i][j],
                                                        // then in-place attn bf16 [ah|al] per row
__device__ float g_o[(size_t)PB * PN * PCI];            // attn out [b][i][c] fp32  8 MB
__device__ bf16  g_qh[(size_t)PB * PN * PCI];           // [b][i][c]  2 MB each
__device__ bf16  g_ql[(size_t)PB * PN * PCI];
__device__ bf16  g_kh[(size_t)PB * PN * PCI];           // [b][j][c]
__device__ bf16  g_kl[(size_t)PB * PN * PCI];
__device__ bf16  g_vh[(size_t)PB * PCI * PN];           // [b][c][j]
__device__ bf16  g_vl[(size_t)PB * PCI * PN];

// ----------------------------------------------------------------------------
// fp32 tiled SGEMM (projection / out-proj GEMMs)
// ----------------------------------------------------------------------------
template<int TM, int TN, bool AKC, bool BNC>
__global__ void __launch_bounds__(256)
gemm_tile(const float* __restrict__ A, long long a_sm, long long a_sk, long long a_sb,
          const float* __restrict__ B, long long b_sk, long long b_sn, long long b_sb,
          float* __restrict__ C, long long c_sm, long long c_sb,
          const float* __restrict__ bias,
          const float* __restrict__ res, long long r_sb,
          int K)
{
    constexpr int TK = 16;
    constexpr int RM = TM / 16;
    constexpr int RN = TN / 16;
    constexpr int A_PT = (TK * TM) / 256;
    constexpr int B_PT = (TK * TN) / 256;

    __shared__ float As[TK][TM + 4];
    __shared__ float Bs[TK][TN + 4];

    const int tid = threadIdx.x;
    const int tx  = tid & 15;
    const int ty  = tid >> 4;
    const int m0  = blockIdx.y * TM;
    const int n0  = blockIdx.x * TN;

    const float* Ab = A + (long long)blockIdx.z * a_sb + (long long)m0 * a_sm;
    const float* Bb = B + (long long)blockIdx.z * b_sb + (long long)n0 * b_sn;

    float acc[RM][RN];
#pragma unroll
    for (int i = 0; i < RM; i++)
#pragma unroll
        for (int j = 0; j < RN; j++) acc[i][j] = 0.0f;

    for (int kt = 0; kt < K; kt += TK) {
#pragma unroll
        for (int i = 0; i < A_PT; i++) {
            int idx = tid + i * 256;
            int m, k;
            if (AKC) { m = idx / TK; k = idx % TK; }
            else     { k = idx / TM; m = idx % TM; }
            As[k][m] = __ldg(&Ab[(long long)m * a_sm + (long long)(kt + k) * a_sk]);
        }
#pragma unroll
        for (int i = 0; i < B_PT; i++) {
            int idx = tid + i * 256;
            int n, k;
            if (BNC) { k = idx / TN; n = idx % TN; }
            else     { n = idx / TK; k = idx % TK; }
            Bs[k][n] = __ldg(&Bb[(long long)(kt + k) * b_sk + (long long)n * b_sn]);
        }
        __syncthreads();

#pragma unroll
        for (int kk = 0; kk < TK; kk++) {
            float a[RM], b[RN];
#pragma unroll
            for (int i = 0; i < RM; i++) a[i] = As[kk][ty * RM + i];
#pragma unroll
            for (int j = 0; j < RN; j++) b[j] = Bs[kk][tx * RN + j];
#pragma unroll
            for (int i = 0; i < RM; i++)
#pragma unroll
                for (int j = 0; j < RN; j++)
                    acc[i][j] += a[i] * b[j];
        }
        __syncthreads();
    }

    float* Cb = C + (long long)blockIdx.z * c_sb;
    const float* Rb = res ? res + (long long)blockIdx.z * r_sb : nullptr;
#pragma unroll
    for (int i = 0; i < RM; i++) {
        const int m = m0 + ty * RM + i;
        const float bv = bias ? bias[m] : 0.0f;
#pragma unroll
        for (int j = 0; j < RN; j++) {
            const int n = n0 + tx * RN + j;
            const long long off = (long long)m * c_sm + n;
            float vvv = acc[i][j] + bv;
            if (Rb) vvv += Rb[off];
            Cb[off] = vvv;
        }
    }
}

// ----------------------------------------------------------------------------
// Tensor-core GEMM, bf16 hi/lo 3-term split:
//   C[b][m][n] = sum_k A[b][m][k] * B[b][n][k]   (fp32 out)
// A as (Ah,Al) row-major [M][lda] (separate base pointers, shared lda/batch),
// B as (Bh,Bl) row-major [N][ldb]. mma.sync.m16n8k16 row.col f32 accumulate.
// ----------------------------------------------------------------------------
template<int BM, int BN, int WM, int WN>
__global__ void __launch_bounds__(256)
mma_gemm3(const bf16* __restrict__ Ah, const bf16* __restrict__ Al,
          long long a_bs, int lda,
          const bf16* __restrict__ Bh, const bf16* __restrict__ Bl,
          long long b_bs, int ldb,
          float* __restrict__ C, long long c_bs, int ldc,
          int K)
{
    constexpr int BK  = 32;
    constexpr int LDS = BK + 8;           // padded row stride; 80 B = 5*16 B
    constexpr int WARPS_M = BM / WM;
    constexpr int MT = WM / 16;
    constexpr int NT = WN / 8;
    constexpr int AV = BM * 8 / 256;
    constexpr int BV = BN * 8 / 256;

    __shared__ bf16 sAh[BM][LDS], sAl[BM][LDS];
    __shared__ bf16 sBh[BN][LDS], sBl[BN][LDS];

    const int tid  = threadIdx.x;
    const int warp = tid >> 5;
    const int lane = tid & 31;
    const int wm = (warp % WARPS_M) * WM;
    const int wn = (warp / WARPS_M) * WN;

    const long long m0 = (long long)blockIdx.y * BM;
    const long long n0 = (long long)blockIdx.x * BN;
    const bf16* Abh = Ah + blockIdx.z * a_bs + m0 * lda;
    const bf16* Abl = Al + blockIdx.z * a_bs + m0 * lda;
    const bf16* Bbh = Bh + blockIdx.z * b_bs + n0 * ldb;
    const bf16* Bbl = Bl + blockIdx.z * b_bs + n0 * ldb;

    float acc[MT][NT][4];
#pragma unroll
    for (int i = 0; i < MT; i++)
#pragma unroll
        for (int j = 0; j < NT; j++)
#pragma unroll
            for (int r = 0; r < 4; r++) acc[i][j][r] = 0.0f;

    const int a_row = lane & 15, a_kh = (lane >> 4) << 3;
    const int b_row = (lane & 7) + ((lane >> 4) << 3), b_kh = lane & 8;

    for (int kt = 0; kt < K; kt += BK) {
#pragma unroll
        for (int i = 0; i < AV; i++) {
            int idx = tid + i * 256, r = idx >> 3, v = (idx & 7) << 2;
            *(uint2*)&sAh[r][v] = *(const uint2*)&Abh[(long long)r * lda + kt + v];
            *(uint2*)&sAl[r][v] = *(const uint2*)&Abl[(long long)r * lda + kt + v];
        }
#pragma unroll
        for (int i = 0; i < BV; i++) {
            int idx = tid + i * 256, r = idx >> 3, v = (idx & 7) << 2;
            *(uint2*)&sBh[r][v] = *(const uint2*)&Bbh[(long long)r * ldb + kt + v];
            *(uint2*)&sBl[r][v] = *(const uint2*)&Bbl[(long long)r * ldb + kt + v];
        }
        __syncthreads();

#pragma unroll
        for (int ks = 0; ks < 2; ks++) {
            const int kc = ks * 16;
            uint32_t afh[MT][4], afl[MT][4];
#pragma unroll
            for (int mt = 0; mt < MT; mt++) {
                uint32_t ah_ = (uint32_t)__cvta_generic_to_shared(&sAh[wm + mt*16 + a_row][kc + a_kh]);
                uint32_t al_ = (uint32_t)__cvta_generic_to_shared(&sAl[wm + mt*16 + a_row][kc + a_kh]);
                asm volatile("ldmatrix.sync.aligned.m8n8.x4.shared.b16 {%0,%1,%2,%3}, [%4];"
                    : "=r"(afh[mt][0]), "=r"(afh[mt][1]), "=r"(afh[mt][2]), "=r"(afh[mt][3]) : "r"(ah_));
                asm volatile("ldmatrix.sync.aligned.m8n8.x4.shared.b16 {%0,%1,%2,%3}, [%4];"
                    : "=r"(afl[mt][0]), "=r"(afl[mt][1]), "=r"(afl[mt][2]), "=r"(afl[mt][3]) : "r"(al_));
            }
            uint32_t bfh[NT][2], bfl[NT][2];
#pragma unroll
            for (int jt = 0; jt < NT; jt += 2) {
                uint32_t bh_ = (uint32_t)__cvta_generic_to_shared(&sBh[wn + jt*8 + b_row][kc + b_kh]);
                uint32_t bl_ = (uint32_t)__cvta_generic_to_shared(&sBl[wn + jt*8 + b_row][kc + b_kh]);
                asm volatile("ldmatrix.sync.aligned.m8n8.x4.shared.b16 {%0,%1,%2,%3}, [%4];"
                    : "=r"(bfh[jt][0]), "=r"(bfh[jt][1]), "=r"(bfh[jt+1][0]), "=r"(bfh[jt+1][1]) : "r"(bh_));
                asm volatile("ldmatrix.sync.aligned.m8n8.x4.shared.b16 {%0,%1,%2,%3}, [%4];"
                    : "=r"(bfl[jt][0]), "=r"(bfl[jt][1]), "=r"(bfl[jt+1][0]), "=r"(bfl[jt+1][1]) : "r"(bl_));
            }
#pragma unroll
            for (int mt = 0; mt < MT; mt++)
#pragma unroll
                for (int jt = 0; jt < NT; jt++) {
                    float* d = acc[mt][jt];
#define MMA_BF16(A0,A1,A2,A3,B0,B1)                                               \
    asm volatile("mma.sync.aligned.m16n8k16.row.col.f32.bf16.bf16.f32 "          \
        "{%0,%1,%2,%3}, {%4,%5,%6,%7}, {%8,%9}, {%0,%1,%2,%3};"                  \
        : "+f"(d[0]), "+f"(d[1]), "+f"(d[2]), "+f"(d[3])                         \
        : "r"(A0), "r"(A1), "r"(A2), "r"(A3), "r"(B0), "r"(B1))
                    MMA_BF16(afh[mt][0], afh[mt][1], afh[mt][2], afh[mt][3], bfh[jt][0], bfh[jt][1]);
                    MMA_BF16(afh[mt][0], afh[mt][1], afh[mt][2], afh[mt][3], bfl[jt][0], bfl[jt][1]);
                    MMA_BF16(afl[mt][0], afl[mt][1], afl[mt][2], afl[mt][3], bfh[jt][0], bfh[jt][1]);
#undef MMA_BF16
                }
        }
        __syncthreads();
    }

    float* Cb = C + blockIdx.z * c_bs;
    const int cr = lane >> 2, cc = (lane & 3) << 1;
#pragma unroll
    for (int mt = 0; mt < MT; mt++)
#pragma unroll
        for (int jt = 0; jt < NT; jt++) {
            long long row = m0 + wm + mt*16 + cr;
            long long col = n0 + wn + jt*8 + cc;
            *(float2*)&Cb[row * ldc + col]       = make_float2(acc[mt][jt][0], acc[mt][jt][1]);
            *(float2*)&Cb[(row + 8) * ldc + col] = make_float2(acc[mt][jt][2], acc[mt][jt][3]);
        }
}

// ----------------------------------------------------------------------------
// Transpose + hi/lo split: src fp32 [b][R][N] -> dh/dl bf16 [b][N][R]
// ----------------------------------------------------------------------------
__global__ void __launch_bounds__(256)
tsplit(const float* __restrict__ src, bf16* __restrict__ dh, bf16* __restrict__ dl, int R)
{
    __shared__ float t[32][33];
    const int tx = threadIdx.x, ty = threadIdx.y;           // 32 x 8
    const long long b = blockIdx.z;
    const int n0 = blockIdx.x * 32, r0 = blockIdx.y * 32;
    const float* S = src + b * (long long)R * PN;
#pragma unroll
    for (int i = 0; i < 4; i++)
        t[ty + i*8][tx] = S[(long long)(r0 + ty + i*8) * PN + n0 + tx];
    __syncthreads();
    bf16* DH = dh + b * (long long)R * PN;
    bf16* DL = dl + b * (long long)R * PN;
#pragma unroll
    for (int i = 0; i < 4; i++) {
        float v = t[tx][ty + i*8];
        bf16 h = __float2bfloat16_rn(v);
        long long off = (long long)(n0 + ty + i*8) * R + r0 + tx;
        DH[off] = h;
        DL[off] = __float2bfloat16_rn(v - __bfloat162float(h));
    }
}

// Elementwise hi/lo split (no transpose): v fp32 -> vh, vl bf16
__global__ void __launch_bounds__(256)
esplit(const float* __restrict__ src, bf16* __restrict__ dh, bf16* __restrict__ dl, long long n)
{
    long long i = (long long)blockIdx.x * 256 + threadIdx.x;
    if (i < n) {
        float v = src[i];
        bf16 h = __float2bfloat16_rn(v);
        dh[i] = h;
        dl[i] = __float2bfloat16_rn(v - __bfloat162float(h));
    }
}

// ----------------------------------------------------------------------------
// Row softmax (N=4096), IN PLACE: reads the fp32 energy row, rewrites the same
// 16 KB row region as [ah row (8 KB bf16) | al row (8 KB bf16)].
// Safe: each block owns exactly one row region; all global reads complete
// before the first __syncthreads, all writes happen after the last one.
// ----------------------------------------------------------------------------
__global__ void __launch_bounds__(256)
softmax_split_inplace(float* __restrict__ e)
{
    constexpr int N = PN;
    constexpr int PT = N / 256;
    float* p = e + (size_t)blockIdx.x * N;
    const int tid = threadIdx.x;

    float v[PT];
    float mx = -1e30f;
#pragma unroll
    for (int i = 0; i < PT; i++) {
        v[i] = p[tid + i * 256];
        mx = fmaxf(mx, v[i]);
    }
    __shared__ float red[256];
    red[tid] = mx;
    __syncthreads();
#pragma unroll
    for (int s = 128; s > 0; s >>= 1) {
        if (tid < s) red[tid] = fmaxf(red[tid], red[tid + s]);
        __syncthreads();
    }
    mx = red[0];
    __syncthreads();
    float sum = 0.0f;
#pragma unroll
    for (int i = 0; i < PT; i++) {
        v[i] = __expf(v[i] - mx);
        sum += v[i];
    }
    red[tid] = sum;
    __syncthreads();
#pragma unroll
    for (int s = 128; s > 0; s >>= 1) {
        if (tid < s) red[tid] += red[tid + s];
        __syncthreads();
    }
    const float inv = 1.0f / red[0];
    bf16* ph = (bf16*)p;            // first half of the row region
    bf16* pl = (bf16*)p + N;        // second half
#pragma unroll
    for (int i = 0; i < PT; i++) {
        float r = v[i] * inv;
        bf16 h = __float2bfloat16_rn(r);
        ph[tid + i * 256] = h;
        pl[tid + i * 256] = __float2bfloat16_rn(r - __bfloat162float(h));
    }
}

// ----------------------------------------------------------------------------
// Launch
// ----------------------------------------------------------------------------
extern "C" void kernel_launch(void* const* d_in, const int* in_sizes, int n_in,
                              void* d_out, int out_size)
{
    (void)in_sizes; (void)n_in; (void)out_size;
    const float* x  = (const float*)d_in[0];
    const float* wq = (const float*)d_in[1];
    const float* bq = (const float*)d_in[2];
    const float* wk = (const float*)d_in[3];
    const float* bk = (const float*)d_in[4];
    const float* wv = (const float*)d_in[5];
    const float* bv = (const float*)d_in[6];
    const float* wo = (const float*)d_in[7];
    const float* bo = (const float*)d_in[8];
    float* out = (float*)d_out;

    static float *q=nullptr,*k=nullptr,*v=nullptr,*e=nullptr,*o=nullptr;
    static bf16 *qh,*ql,*kh,*kl,*vh,*vl;
    if (!q) {
        cudaGetSymbolAddress((void**)&q,  g_q);
        cudaGetSymbolAddress((void**)&k,  g_k);
        cudaGetSymbolAddress((void**)&v,  g_v);
        cudaGetSymbolAddress((void**)&e,  g_e);
        cudaGetSymbolAddress((void**)&o,  g_o);
        cudaGetSymbolAddress((void**)&qh, g_qh);
        cudaGetSymbolAddress((void**)&ql, g_ql);
        cudaGetSymbolAddress((void**)&kh, g_kh);
        cudaGetSymbolAddress((void**)&kl, g_kl);
        cudaGetSymbolAddress((void**)&vh, g_vh);
        cudaGetSymbolAddress((void**)&vl, g_vl);
    }

    const long long N = PN, C = PC, CI = PCI;
    const long long xsb = C * N;          // x batch stride
    const long long qsb = CI * N;         // q/k/v batch stride (fp32, [c][n])
    const long long tsb = N * CI;         // qh/kh batch stride ([n][c])
    const long long esb = N * N;          // energy batch stride (fp32 elems)
    dim3 blk(256);

    // 1) q/k/v projections (fp32): [CI,C] x [C,N] + bias -> [b][ci][n]
    gemm_tile<128,128,true,true><<<dim3(PN/128, PCI/128, PB), blk>>>(
        wq, C, 1, 0,  x, N, 1, xsb,  q, N, qsb,  bq, nullptr, 0, (int)C);
    gemm_tile<128,128,true,true><<<dim3(PN/128, PCI/128, PB), blk>>>(
        wk, C, 1, 0,  x, N, 1, xsb,  k, N, qsb,  bk, nullptr, 0, (int)C);
    gemm_tile<128,128,true,true><<<dim3(PN/128, PCI/128, PB), blk>>>(
        wv, C, 1, 0,  x, N, 1, xsb,  v, N, qsb,  bv, nullptr, 0, (int)C);

    // 2) convert: q,k -> transposed hi/lo bf16 [n][c]; v -> hi/lo bf16 [c][j]
    tsplit<<<dim3(PN/32, PCI/32, PB), dim3(32,8)>>>(q, qh, ql, PCI);
    tsplit<<<dim3(PN/32, PCI/32, PB), dim3(32,8)>>>(k, kh, kl, PCI);
    esplit<<<(int)((PB*qsb + 255)/256), blk>>>(v, vh, vl, PB*qsb);

    // 3) energy = Q^T K via tensor cores: A=qh[i][c], B=kh[j][c], C=e[i][j]
    mma_gemm3<128,128,32,64><<<dim3(PN/128, PN/128, PB), blk>>>(
        qh, ql, tsb, PCI,  kh, kl, tsb, PCI,  e, esb, PN, PCI);

    // 4) softmax rows -> attn hi/lo bf16, packed in place into g_e
    softmax_split_inplace<<<PB * PN, blk>>>(e);

    // 5) O[i][c] = sum_j attn[i][j] v[c][j]
    //    Ah=(bf16*)e row-stride 2N (row region = [ah|al]), Al = Ah + N
    mma_gemm3<64,128,32,32><<<dim3(PCI/128, PN/64, PB), blk>>>(
        (const bf16*)e, (const bf16*)e + PN, 2*esb, 2*PN,
        vh, vl, qsb, PN,
        o, (long long)PN*PCI, PCI, PN);

    // 6) out = wo * O^T + bo + x   (B = O[i][ci]: contiguous along k)
    gemm_tile<128,128,true,false><<<dim3(PN/128, PC/128, PB), blk>>>(
        wo, CI, 1, 0,  o, 1, CI, (long long)PN*PCI,  out, N, xsb,  bo, x, xsb, (int)CI);
}

// round 8
// speedup vs baseline: 2.5589x; 1.2582x over previous
#include <cuda_runtime.h>
#include <cuda_bf16.h>
#include <cstdint>

// Problem constants: B=4, C=512, CI=128, H=W=64, N=4096
#define PB  4
#define PC  512
#define PCI 128
#define PN  4096

typedef __nv_bfloat16 bf16;

// ---------------- scratch (~309 MB of __device__ globals) -------------------
// g_e serves double duty: (phase A) xth/xtl transpose-split scratch (33.6 MB,
// dead after the q/k/v projection GEMMs), then (phase B) fp32 energy ->
// in-place bf16 attn [ah|al]. Energy GEMM is the first writer of g_e and
// reads only q/k buffers, so phase A data is dead before it's overwritten.
__device__ float g_e[(size_t)PB * PN * PN];              // 268 MB
__device__ bf16  g_qh[(size_t)PB * PN * PCI];            // [b][i][ci] 4 MB each
__device__ bf16  g_ql[(size_t)PB * PN * PCI];
__device__ bf16  g_kh[(size_t)PB * PN * PCI];
__device__ bf16  g_kl[(size_t)PB * PN * PCI];
__device__ bf16  g_vh[(size_t)PB * PCI * PN];            // [b][ci][j]
__device__ bf16  g_vl[(size_t)PB * PCI * PN];
__device__ bf16  g_oh[(size_t)PB * PN * PCI];            // [b][i][ci]
__device__ bf16  g_ol[(size_t)PB * PN * PCI];
__device__ bf16  g_wqh[PCI * PC], g_wql[PCI * PC];
__device__ bf16  g_wkh[PCI * PC], g_wkl[PCI * PC];
__device__ bf16  g_wvh[PCI * PC], g_wvl[PCI * PC];
__device__ bf16  g_woh[PC * PCI], g_wol[PC * PCI];

// ----------------------------------------------------------------------------
// Tensor-core GEMM, bf16 hi/lo 3-term split:
//   C[b][m][n] = sum_k A[b][m][k] * B[b][n][k]
// OMODE: 0 = fp32 out (C, optional residual res), 1 = bf16 hi/lo out (Dh, Dl)
// BMODE: 0 = no bias, 1 = bias[m] (row), 2 = bias[n] (col)
// ----------------------------------------------------------------------------
template<int BM, int BN, int WM, int WN, int OMODE, int BMODE>
__global__ void __launch_bounds__(256)
mma_gemm3(const bf16* __restrict__ Ah, const bf16* __restrict__ Al,
          long long a_bs, int lda,
          const bf16* __restrict__ Bh, const bf16* __restrict__ Bl,
          long long b_bs, int ldb,
          float* __restrict__ C, bf16* __restrict__ Dh, bf16* __restrict__ Dl,
          long long c_bs, int ldc,
          const float* __restrict__ bias,
          const float* __restrict__ res, long long r_sb,
          int K)
{
    constexpr int BK  = 32;
    constexpr int LDS = BK + 8;           // padded row stride; 80 B = 5*16 B
    constexpr int WARPS_M = BM / WM;
    constexpr int MT = WM / 16;
    constexpr int NT = WN / 8;
    constexpr int AV = BM * 8 / 256;
    constexpr int BV = BN * 8 / 256;

    __shared__ bf16 sAh[BM][LDS], sAl[BM][LDS];
    __shared__ bf16 sBh[BN][LDS], sBl[BN][LDS];

    const int tid  = threadIdx.x;
    const int warp = tid >> 5;
    const int lane = tid & 31;
    const int wm = (warp % WARPS_M) * WM;
    const int wn = (warp / WARPS_M) * WN;

    const long long m0 = (long long)blockIdx.y * BM;
    const long long n0 = (long long)blockIdx.x * BN;
    const bf16* Abh = Ah + blockIdx.z * a_bs + m0 * lda;
    const bf16* Abl = Al + blockIdx.z * a_bs + m0 * lda;
    const bf16* Bbh = Bh + blockIdx.z * b_bs + n0 * ldb;
    const bf16* Bbl = Bl + blockIdx.z * b_bs + n0 * ldb;

    float acc[MT][NT][4];
#pragma unroll
    for (int i = 0; i < MT; i++)
#pragma unroll
        for (int j = 0; j < NT; j++)
#pragma unroll
            for (int r = 0; r < 4; r++) acc[i][j][r] = 0.0f;

    const int a_row = lane & 15, a_kh = (lane >> 4) << 3;
    const int b_row = (lane & 7) + ((lane >> 4) << 3), b_kh = lane & 8;

    for (int kt = 0; kt < K; kt += BK) {
#pragma unroll
        for (int i = 0; i < AV; i++) {
            int idx = tid + i * 256, r = idx >> 3, v = (idx & 7) << 2;
            *(uint2*)&sAh[r][v] = *(const uint2*)&Abh[(long long)r * lda + kt + v];
            *(uint2*)&sAl[r][v] = *(const uint2*)&Abl[(long long)r * lda + kt + v];
        }
#pragma unroll
        for (int i = 0; i < BV; i++) {
            int idx = tid + i * 256, r = idx >> 3, v = (idx & 7) << 2;
            *(uint2*)&sBh[r][v] = *(const uint2*)&Bbh[(long long)r * ldb + kt + v];
            *(uint2*)&sBl[r][v] = *(const uint2*)&Bbl[(long long)r * ldb + kt + v];
        }
        __syncthreads();

#pragma unroll
        for (int ks = 0; ks < 2; ks++) {
            const int kc = ks * 16;
            uint32_t afh[MT][4], afl[MT][4];
#pragma unroll
            for (int mt = 0; mt < MT; mt++) {
                uint32_t ah_ = (uint32_t)__cvta_generic_to_shared(&sAh[wm + mt*16 + a_row][kc + a_kh]);
                uint32_t al_ = (uint32_t)__cvta_generic_to_shared(&sAl[wm + mt*16 + a_row][kc + a_kh]);
                asm volatile("ldmatrix.sync.aligned.m8n8.x4.shared.b16 {%0,%1,%2,%3}, [%4];"
                    : "=r"(afh[mt][0]), "=r"(afh[mt][1]), "=r"(afh[mt][2]), "=r"(afh[mt][3]) : "r"(ah_));
                asm volatile("ldmatrix.sync.aligned.m8n8.x4.shared.b16 {%0,%1,%2,%3}, [%4];"
                    : "=r"(afl[mt][0]), "=r"(afl[mt][1]), "=r"(afl[mt][2]), "=r"(afl[mt][3]) : "r"(al_));
            }
            uint32_t bfh[NT][2], bfl[NT][2];
#pragma unroll
            for (int jt = 0; jt < NT; jt += 2) {
                uint32_t bh_ = (uint32_t)__cvta_generic_to_shared(&sBh[wn + jt*8 + b_row][kc + b_kh]);
                uint32_t bl_ = (uint32_t)__cvta_generic_to_shared(&sBl[wn + jt*8 + b_row][kc + b_kh]);
                asm volatile("ldmatrix.sync.aligned.m8n8.x4.shared.b16 {%0,%1,%2,%3}, [%4];"
                    : "=r"(bfh[jt][0]), "=r"(bfh[jt][1]), "=r"(bfh[jt+1][0]), "=r"(bfh[jt+1][1]) : "r"(bh_));
                asm volatile("ldmatrix.sync.aligned.m8n8.x4.shared.b16 {%0,%1,%2,%3}, [%4];"
                    : "=r"(bfl[jt][0]), "=r"(bfl[jt][1]), "=r"(bfl[jt+1][0]), "=r"(bfl[jt+1][1]) : "r"(bl_));
            }
#pragma unroll
            for (int mt = 0; mt < MT; mt++)
#pragma unroll
                for (int jt = 0; jt < NT; jt++) {
                    float* d = acc[mt][jt];
#define MMA_BF16(A0,A1,A2,A3,B0,B1)                                               \
    asm volatile("mma.sync.aligned.m16n8k16.row.col.f32.bf16.bf16.f32 "          \
        "{%0,%1,%2,%3}, {%4,%5,%6,%7}, {%8,%9}, {%0,%1,%2,%3};"                  \
        : "+f"(d[0]), "+f"(d[1]), "+f"(d[2]), "+f"(d[3])                         \
        : "r"(A0), "r"(A1), "r"(A2), "r"(A3), "r"(B0), "r"(B1))
                    MMA_BF16(afh[mt][0], afh[mt][1], afh[mt][2], afh[mt][3], bfh[jt][0], bfh[jt][1]);
                    MMA_BF16(afh[mt][0], afh[mt][1], afh[mt][2], afh[mt][3], bfl[jt][0], bfl[jt][1]);
                    MMA_BF16(afl[mt][0], afl[mt][1], afl[mt][2], afl[mt][3], bfh[jt][0], bfh[jt][1]);
#undef MMA_BF16
                }
        }
        __syncthreads();
    }

    // ---- epilogue ----
    const int cr = lane >> 2, cc = (lane & 3) << 1;
    if (OMODE == 0) {
        float* Cb = C + blockIdx.z * c_bs;
        const float* Rb = res ? res + blockIdx.z * r_sb : nullptr;
#pragma unroll
        for (int mt = 0; mt < MT; mt++)
#pragma unroll
            for (int jt = 0; jt < NT; jt++) {
#pragma unroll
                for (int half = 0; half < 2; half++) {
                    long long row = m0 + wm + mt*16 + cr + half*8;
                    long long col = n0 + wn + jt*8 + cc;
                    float v0 = acc[mt][jt][half*2 + 0];
                    float v1 = acc[mt][jt][half*2 + 1];
                    if (BMODE == 1) { float bv = bias[row]; v0 += bv; v1 += bv; }
                    else if (BMODE == 2) { v0 += bias[col]; v1 += bias[col + 1]; }
                    if (Rb) {
                        const float2 rv = *(const float2*)&Rb[row * ldc + col];
                        v0 += rv.x; v1 += rv.y;
                    }
                    *(float2*)&Cb[row * ldc + col] = make_float2(v0, v1);
                }
            }
    } else {
        bf16* DhB = Dh + blockIdx.z * c_bs;
        bf16* DlB = Dl + blockIdx.z * c_bs;
#pragma unroll
        for (int mt = 0; mt < MT; mt++)
#pragma unroll
            for (int jt = 0; jt < NT; jt++) {
#pragma unroll
                for (int half = 0; half < 2; half++) {
                    long long row = m0 + wm + mt*16 + cr + half*8;
                    long long col = n0 + wn + jt*8 + cc;
                    float v0 = acc[mt][jt][half*2 + 0];
                    float v1 = acc[mt][jt][half*2 + 1];
                    if (BMODE == 1) { float bv = bias[row]; v0 += bv; v1 += bv; }
                    else if (BMODE == 2) { v0 += bias[col]; v1 += bias[col + 1]; }
                    bf16 h0 = __float2bfloat16_rn(v0);
                    bf16 h1 = __float2bfloat16_rn(v1);
                    __nv_bfloat162 hp; hp.x = h0; hp.y = h1;
                    __nv_bfloat162 lp;
                    lp.x = __float2bfloat16_rn(v0 - __bfloat162float(h0));
                    lp.y = __float2bfloat16_rn(v1 - __bfloat162float(h1));
                    *(__nv_bfloat162*)&DhB[row * ldc + col] = hp;
                    *(__nv_bfloat162*)&DlB[row * ldc + col] = lp;
                }
            }
    }
}

// ----------------------------------------------------------------------------
// Transpose + hi/lo split: src fp32 [b][R][N] -> dh/dl bf16 [b][N][R]
// ----------------------------------------------------------------------------
__global__ void __launch_bounds__(256)
tsplit(const float* __restrict__ src, bf16* __restrict__ dh, bf16* __restrict__ dl, int R)
{
    __shared__ float t[32][33];
    const int tx = threadIdx.x, ty = threadIdx.y;           // 32 x 8
    const long long b = blockIdx.z;
    const int n0 = blockIdx.x * 32, r0 = blockIdx.y * 32;
    const float* S = src + b * (long long)R * PN;
#pragma unroll
    for (int i = 0; i < 4; i++)
        t[ty + i*8][tx] = S[(long long)(r0 + ty + i*8) * PN + n0 + tx];
    __syncthreads();
    bf16* DH = dh + b * (long long)R * PN;
    bf16* DL = dl + b * (long long)R * PN;
#pragma unroll
    for (int i = 0; i < 4; i++) {
        float v = t[tx][ty + i*8];
        bf16 h = __float2bfloat16_rn(v);
        long long off = (long long)(n0 + ty + i*8) * R + r0 + tx;
        DH[off] = h;
        DL[off] = __float2bfloat16_rn(v - __bfloat162float(h));
    }
}

// Elementwise hi/lo split (weights): fp32 -> bf16 h/l
__global__ void __launch_bounds__(256)
esplit(const float* __restrict__ src, bf16* __restrict__ dh, bf16* __restrict__ dl, int n)
{
    int i = blockIdx.x * 256 + threadIdx.x;
    if (i < n) {
        float v = src[i];
        bf16 h = __float2bfloat16_rn(v);
        dh[i] = h;
        dl[i] = __float2bfloat16_rn(v - __bfloat162float(h));
    }
}

// ----------------------------------------------------------------------------
// Row softmax (N=4096), IN PLACE: fp32 energy row -> [ah (bf16) | al (bf16)]
// ----------------------------------------------------------------------------
__global__ void __launch_bounds__(256)
softmax_split_inplace(float* __restrict__ e)
{
    constexpr int N = PN;
    constexpr int PT = N / 256;
    float* p = e + (size_t)blockIdx.x * N;
    const int tid = threadIdx.x;

    float v[PT];
    float mx = -1e30f;
#pragma unroll
    for (int i = 0; i < PT; i++) {
        v[i] = p[tid + i * 256];
        mx = fmaxf(mx, v[i]);
    }
    __shared__ float red[256];
    red[tid] = mx;
    __syncthreads();
#pragma unroll
    for (int s = 128; s > 0; s >>= 1) {
        if (tid < s) red[tid] = fmaxf(red[tid], red[tid + s]);
        __syncthreads();
    }
    mx = red[0];
    __syncthreads();
    float sum = 0.0f;
#pragma unroll
    for (int i = 0; i < PT; i++) {
        v[i] = __expf(v[i] - mx);
        sum += v[i];
    }
    red[tid] = sum;
    __syncthreads();
#pragma unroll
    for (int s = 128; s > 0; s >>= 1) {
        if (tid < s) red[tid] += red[tid + s];
        __syncthreads();
    }
    const float inv = 1.0f / red[0];
    bf16* ph = (bf16*)p;
    bf16* pl = (bf16*)p + N;
#pragma unroll
    for (int i = 0; i < PT; i++) {
        float r = v[i] * inv;
        bf16 h = __float2bfloat16_rn(r);
        ph[tid + i * 256] = h;
        pl[tid + i * 256] = __float2bfloat16_rn(r - __bfloat162float(h));
    }
}

// ----------------------------------------------------------------------------
// Launch
// ----------------------------------------------------------------------------
extern "C" void kernel_launch(void* const* d_in, const int* in_sizes, int n_in,
                              void* d_out, int out_size)
{
    (void)in_sizes; (void)n_in; (void)out_size;
    const float* x  = (const float*)d_in[0];
    const float* wq = (const float*)d_in[1];
    const float* bq = (const float*)d_in[2];
    const float* wk = (const float*)d_in[3];
    const float* bk = (const float*)d_in[4];
    const float* wv = (const float*)d_in[5];
    const float* bv = (const float*)d_in[6];
    const float* wo = (const float*)d_in[7];
    const float* bo = (const float*)d_in[8];
    float* out = (float*)d_out;

    static float *e = nullptr;
    static bf16 *xth,*xtl,*qh,*ql,*kh,*kl,*vh,*vl,*oh,*ol;
    static bf16 *wqh,*wql,*wkh,*wkl,*wvh,*wvl,*woh,*wol;
    if (!e) {
        cudaGetSymbolAddress((void**)&e,   g_e);
        cudaGetSymbolAddress((void**)&qh,  g_qh);
        cudaGetSymbolAddress((void**)&ql,  g_ql);
        cudaGetSymbolAddress((void**)&kh,  g_kh);
        cudaGetSymbolAddress((void**)&kl,  g_kl);
        cudaGetSymbolAddress((void**)&vh,  g_vh);
        cudaGetSymbolAddress((void**)&vl,  g_vl);
        cudaGetSymbolAddress((void**)&oh,  g_oh);
        cudaGetSymbolAddress((void**)&ol,  g_ol);
        cudaGetSymbolAddress((void**)&wqh, g_wqh);
        cudaGetSymbolAddress((void**)&wql, g_wql);
        cudaGetSymbolAddress((void**)&wkh, g_wkh);
        cudaGetSymbolAddress((void**)&wkl, g_wkl);
        cudaGetSymbolAddress((void**)&wvh, g_wvh);
        cudaGetSymbolAddress((void**)&wvl, g_wvl);
        cudaGetSymbolAddress((void**)&woh, g_woh);
        cudaGetSymbolAddress((void**)&wol, g_wol);
        // Phase-A aliases inside g_e: xth | xtl (dead before energy GEMM writes g_e)
        xth = (bf16*)e;
        xtl = xth + (size_t)PB * PN * PC;
    }

    const long long N = PN, C = PC, CI = PCI;
    const long long xsb = C * N;          // x / out batch stride
    const long long tsb = N * C;          // xt batch stride [n][c]
    const long long qsb = N * CI;         // q/k/o batch stride [i][ci]
    const long long vsb = CI * N;         // v batch stride [ci][j]
    const long long esb = N * N;
    dim3 blk(256);

    // 0) split x (transposed, into g_e scratch) + weights
    tsplit<<<dim3(PN/32, PC/32, PB), dim3(32,8)>>>(x, xth, xtl, PC);
    esplit<<<PCI*PC/256, blk>>>(wq, wqh, wql, PCI*PC);
    esplit<<<PCI*PC/256, blk>>>(wk, wkh, wkl, PCI*PC);
    esplit<<<PCI*PC/256, blk>>>(wv, wvh, wvl, PCI*PC);
    esplit<<<PC*PCI/256, blk>>>(wo, woh, wol, PC*PCI);

    // 1) q,k: C[i][ci] = sum_c xt[i][c] * wq[ci][c]  (+bq per col) -> bf16 h/l
    mma_gemm3<64,128,32,32,1,2><<<dim3(1, PN/64, PB), blk>>>(
        xth, xtl, tsb, PC,  wqh, wql, 0, PC,
        nullptr, qh, ql, qsb, PCI,  bq, nullptr, 0, PC);
    mma_gemm3<64,128,32,32,1,2><<<dim3(1, PN/64, PB), blk>>>(
        xth, xtl, tsb, PC,  wkh, wkl, 0, PC,
        nullptr, kh, kl, qsb, PCI,  bk, nullptr, 0, PC);

    // 2) v: C[ci][j] = sum_c wv[ci][c] * xt[j][c]  (+bv per row) -> bf16 h/l
    mma_gemm3<64,128,32,32,1,1><<<dim3(PN/128, PCI/64, PB), blk>>>(
        wvh, wvl, 0, PC,  xth, xtl, tsb, PC,
        nullptr, vh, vl, vsb, PN,  bv, nullptr, 0, PC);

    // 3) energy[i][j] = sum_ci q[i][ci] k[j][ci]  -> fp32 (first writer of g_e)
    mma_gemm3<128,128,32,64,0,0><<<dim3(PN/128, PN/128, PB), blk>>>(
        qh, ql, qsb, PCI,  kh, kl, qsb, PCI,
        e, nullptr, nullptr, esb, PN,  nullptr, nullptr, 0, PCI);

    // 4) softmax rows -> attn bf16 h/l packed in place
    softmax_split_inplace<<<PB * PN, blk>>>(e);

    // 5) O[i][ci] = sum_j attn[i][j] v[ci][j]  -> bf16 h/l
    mma_gemm3<64,128,32,32,1,0><<<dim3(1, PN/64, PB), blk>>>(
        (const bf16*)e, (const bf16*)e + PN, 2*esb, 2*PN,
        vh, vl, vsb, PN,
        nullptr, oh, ol, qsb, PCI,  nullptr, nullptr, 0, PN);

    // 6) out[c][n] = sum_ci wo[c][ci] * O[n][ci] + bo + x  -> fp32 d_out
    mma_gemm3<128,128,32,64,0,1><<<dim3(PN/128, PC/128, PB), blk>>>(
        woh, wol, 0, PCI,  oh, ol, qsb, PCI,
        out, nullptr, nullptr, xsb, PN,  bo, x, xsb, PCI);
}

// round 9
// speedup vs baseline: 2.7094x; 1.0588x over previous
#include <cuda_runtime.h>
#include <cuda_bf16.h>
#include <cstdint>

// Problem constants: B=4, C=512, CI=128, H=W=64, N=4096
#define PB  4
#define PC  512
#define PCI 128
#define PN  4096

typedef __nv_bfloat16 bf16;

// ---------------- scratch (~309 MB of __device__ globals) -------------------
// g_e serves double duty: (phase A) xth/xtl transpose-split scratch (33.6 MB,
// dead after the q/k/v projection GEMMs), then (phase B) fp32 energy ->
// in-place bf16 attn [ah|al]. Energy GEMM is the first writer of g_e and
// reads only q/k buffers, so phase A data is dead before it's overwritten.
__device__ float g_e[(size_t)PB * PN * PN];              // 268 MB
__device__ bf16  g_qh[(size_t)PB * PN * PCI];            // [b][i][ci] 4 MB each
__device__ bf16  g_ql[(size_t)PB * PN * PCI];
__device__ bf16  g_kh[(size_t)PB * PN * PCI];
__device__ bf16  g_kl[(size_t)PB * PN * PCI];
__device__ bf16  g_vh[(size_t)PB * PCI * PN];            // [b][ci][j]
__device__ bf16  g_vl[(size_t)PB * PCI * PN];
__device__ bf16  g_oh[(size_t)PB * PN * PCI];            // [b][i][ci]
__device__ bf16  g_ol[(size_t)PB * PN * PCI];
__device__ bf16  g_wqh[PCI * PC], g_wql[PCI * PC];
__device__ bf16  g_wkh[PCI * PC], g_wkl[PCI * PC];
__device__ bf16  g_wvh[PCI * PC], g_wvl[PCI * PC];
__device__ bf16  g_woh[PC * PCI], g_wol[PC * PCI];

// ----------------------------------------------------------------------------
// Tensor-core GEMM, bf16 hi/lo 3-term split, register-prefetch pipelined:
//   C[b][m][n] = sum_k A[b][m][k] * B[b][n][k]
// OMODE: 0 = fp32 out (C, optional residual res), 1 = bf16 hi/lo out (Dh, Dl)
// BMODE: 0 = no bias, 1 = bias[m] (row), 2 = bias[n] (col)
// ----------------------------------------------------------------------------
template<int BM, int BN, int WM, int WN, int OMODE, int BMODE>
__global__ void __launch_bounds__(256)
mma_gemm3(const bf16* __restrict__ Ah, const bf16* __restrict__ Al,
          long long a_bs, int lda,
          const bf16* __restrict__ Bh, const bf16* __restrict__ Bl,
          long long b_bs, int ldb,
          float* __restrict__ C, bf16* __restrict__ Dh, bf16* __restrict__ Dl,
          long long c_bs, int ldc,
          const float* __restrict__ bias,
          const float* __restrict__ res, long long r_sb,
          int K)
{
    constexpr int BK  = 32;
    constexpr int LDS = BK + 8;           // padded row stride; 80 B = 5*16 B
    constexpr int WARPS_M = BM / WM;
    constexpr int MT = WM / 16;
    constexpr int NT = WN / 8;
    constexpr int AV = BM * 8 / 256;
    constexpr int BV = BN * 8 / 256;

    __shared__ bf16 sAh[BM][LDS], sAl[BM][LDS];
    __shared__ bf16 sBh[BN][LDS], sBl[BN][LDS];

    const int tid  = threadIdx.x;
    const int warp = tid >> 5;
    const int lane = tid & 31;
    const int wm = (warp % WARPS_M) * WM;
    const int wn = (warp / WARPS_M) * WN;

    const long long m0 = (long long)blockIdx.y * BM;
    const long long n0 = (long long)blockIdx.x * BN;
    const bf16* Abh = Ah + blockIdx.z * a_bs + m0 * lda;
    const bf16* Abl = Al + blockIdx.z * a_bs + m0 * lda;
    const bf16* Bbh = Bh + blockIdx.z * b_bs + n0 * ldb;
    const bf16* Bbl = Bl + blockIdx.z * b_bs + n0 * ldb;

    float acc[MT][NT][4];
#pragma unroll
    for (int i = 0; i < MT; i++)
#pragma unroll
        for (int j = 0; j < NT; j++)
#pragma unroll
            for (int r = 0; r < 4; r++) acc[i][j][r] = 0.0f;

    const int a_row = lane & 15, a_kh = (lane >> 4) << 3;
    const int b_row = (lane & 7) + ((lane >> 4) << 3), b_kh = lane & 8;

    // ---- register staging for the software pipeline ----
    uint2 pah[AV], pal[AV], pbh[BV], pbl[BV];
    const int ar = (tid) >> 3;                 // base row for this thread (idx i adds 32)
    const int av = (tid & 7) << 2;

#define PREFETCH(kt_)                                                             \
    {                                                                             \
        _Pragma("unroll")                                                         \
        for (int i = 0; i < AV; i++) {                                            \
            int r = ar + i * 32;                                                  \
            pah[i] = *(const uint2*)&Abh[(long long)r * lda + (kt_) + av];        \
            pal[i] = *(const uint2*)&Abl[(long long)r * lda + (kt_) + av];        \
        }                                                                         \
        _Pragma("unroll")                                                         \
        for (int i = 0; i < BV; i++) {                                            \
            int r = ar + i * 32;                                                  \
            pbh[i] = *(const uint2*)&Bbh[(long long)r * ldb + (kt_) + av];        \
            pbl[i] = *(const uint2*)&Bbl[(long long)r * ldb + (kt_) + av];        \
        }                                                                         \
    }

    PREFETCH(0);

    for (int kt = 0; kt < K; kt += BK) {
        // ---- drain staged registers into smem ----
#pragma unroll
        for (int i = 0; i < AV; i++) {
            int r = ar + i * 32;
            *(uint2*)&sAh[r][av] = pah[i];
            *(uint2*)&sAl[r][av] = pal[i];
        }
#pragma unroll
        for (int i = 0; i < BV; i++) {
            int r = ar + i * 32;
            *(uint2*)&sBh[r][av] = pbh[i];
            *(uint2*)&sBl[r][av] = pbl[i];
        }
        __syncthreads();

        // ---- prefetch next tile (overlaps with the mma work below) ----
        if (kt + BK < K) PREFETCH(kt + BK);

#pragma unroll
        for (int ks = 0; ks < 2; ks++) {
            const int kc = ks * 16;
            uint32_t afh[MT][4], afl[MT][4];
#pragma unroll
            for (int mt = 0; mt < MT; mt++) {
                uint32_t ah_ = (uint32_t)__cvta_generic_to_shared(&sAh[wm + mt*16 + a_row][kc + a_kh]);
                uint32_t al_ = (uint32_t)__cvta_generic_to_shared(&sAl[wm + mt*16 + a_row][kc + a_kh]);
                asm volatile("ldmatrix.sync.aligned.m8n8.x4.shared.b16 {%0,%1,%2,%3}, [%4];"
                    : "=r"(afh[mt][0]), "=r"(afh[mt][1]), "=r"(afh[mt][2]), "=r"(afh[mt][3]) : "r"(ah_));
                asm volatile("ldmatrix.sync.aligned.m8n8.x4.shared.b16 {%0,%1,%2,%3}, [%4];"
                    : "=r"(afl[mt][0]), "=r"(afl[mt][1]), "=r"(afl[mt][2]), "=r"(afl[mt][3]) : "r"(al_));
            }
            uint32_t bfh[NT][2], bfl[NT][2];
#pragma unroll
            for (int jt = 0; jt < NT; jt += 2) {
                uint32_t bh_ = (uint32_t)__cvta_generic_to_shared(&sBh[wn + jt*8 + b_row][kc + b_kh]);
                uint32_t bl_ = (uint32_t)__cvta_generic_to_shared(&sBl[wn + jt*8 + b_row][kc + b_kh]);
                asm volatile("ldmatrix.sync.aligned.m8n8.x4.shared.b16 {%0,%1,%2,%3}, [%4];"
                    : "=r"(bfh[jt][0]), "=r"(bfh[jt][1]), "=r"(bfh[jt+1][0]), "=r"(bfh[jt+1][1]) : "r"(bh_));
                asm volatile("ldmatrix.sync.aligned.m8n8.x4.shared.b16 {%0,%1,%2,%3}, [%4];"
                    : "=r"(bfl[jt][0]), "=r"(bfl[jt][1]), "=r"(bfl[jt+1][0]), "=r"(bfl[jt+1][1]) : "r"(bl_));
            }
#pragma unroll
            for (int mt = 0; mt < MT; mt++)
#pragma unroll
                for (int jt = 0; jt < NT; jt++) {
                    float* d = acc[mt][jt];
#define MMA_BF16(A0,A1,A2,A3,B0,B1)                                               \
    asm volatile("mma.sync.aligned.m16n8k16.row.col.f32.bf16.bf16.f32 "          \
        "{%0,%1,%2,%3}, {%4,%5,%6,%7}, {%8,%9}, {%0,%1,%2,%3};"                  \
        : "+f"(d[0]), "+f"(d[1]), "+f"(d[2]), "+f"(d[3])                         \
        : "r"(A0), "r"(A1), "r"(A2), "r"(A3), "r"(B0), "r"(B1))
                    MMA_BF16(afh[mt][0], afh[mt][1], afh[mt][2], afh[mt][3], bfh[jt][0], bfh[jt][1]);
                    MMA_BF16(afh[mt][0], afh[mt][1], afh[mt][2], afh[mt][3], bfl[jt][0], bfl[jt][1]);
                    MMA_BF16(afl[mt][0], afl[mt][1], afl[mt][2], afl[mt][3], bfh[jt][0], bfh[jt][1]);
#undef MMA_BF16
                }
        }
        __syncthreads();
    }
#undef PREFETCH

    // ---- epilogue ----
    const int cr = lane >> 2, cc = (lane & 3) << 1;
    if (OMODE == 0) {
        float* Cb = C + blockIdx.z * c_bs;
        const float* Rb = res ? res + blockIdx.z * r_sb : nullptr;
#pragma unroll
        for (int mt = 0; mt < MT; mt++)
#pragma unroll
            for (int jt = 0; jt < NT; jt++) {
#pragma unroll
                for (int half = 0; half < 2; half++) {
                    long long row = m0 + wm + mt*16 + cr + half*8;
                    long long col = n0 + wn + jt*8 + cc;
                    float v0 = acc[mt][jt][half*2 + 0];
                    float v1 = acc[mt][jt][half*2 + 1];
                    if (BMODE == 1) { float bv = bias[row]; v0 += bv; v1 += bv; }
                    else if (BMODE == 2) { v0 += bias[col]; v1 += bias[col + 1]; }
                    if (Rb) {
                        const float2 rv = *(const float2*)&Rb[row * ldc + col];
                        v0 += rv.x; v1 += rv.y;
                    }
                    *(float2*)&Cb[row * ldc + col] = make_float2(v0, v1);
                }
            }
    } else {
        bf16* DhB = Dh + blockIdx.z * c_bs;
        bf16* DlB = Dl + blockIdx.z * c_bs;
#pragma unroll
        for (int mt = 0; mt < MT; mt++)
#pragma unroll
            for (int jt = 0; jt < NT; jt++) {
#pragma unroll
                for (int half = 0; half < 2; half++) {
                    long long row = m0 + wm + mt*16 + cr + half*8;
                    long long col = n0 + wn + jt*8 + cc;
                    float v0 = acc[mt][jt][half*2 + 0];
                    float v1 = acc[mt][jt][half*2 + 1];
                    if (BMODE == 1) { float bv = bias[row]; v0 += bv; v1 += bv; }
                    else if (BMODE == 2) { v0 += bias[col]; v1 += bias[col + 1]; }
                    bf16 h0 = __float2bfloat16_rn(v0);
                    bf16 h1 = __float2bfloat16_rn(v1);
                    __nv_bfloat162 hp; hp.x = h0; hp.y = h1;
                    __nv_bfloat162 lp;
                    lp.x = __float2bfloat16_rn(v0 - __bfloat162float(h0));
                    lp.y = __float2bfloat16_rn(v1 - __bfloat162float(h1));
                    *(__nv_bfloat162*)&DhB[row * ldc + col] = hp;
                    *(__nv_bfloat162*)&DlB[row * ldc + col] = lp;
                }
            }
    }
}

// ----------------------------------------------------------------------------
// Transpose + hi/lo split: src fp32 [b][R][N] -> dh/dl bf16 [b][N][R]
// ----------------------------------------------------------------------------
__global__ void __launch_bounds__(256)
tsplit(const float* __restrict__ src, bf16* __restrict__ dh, bf16* __restrict__ dl, int R)
{
    __shared__ float t[32][33];
    const int tx = threadIdx.x, ty = threadIdx.y;           // 32 x 8
    const long long b = blockIdx.z;
    const int n0 = blockIdx.x * 32, r0 = blockIdx.y * 32;
    const float* S = src + b * (long long)R * PN;
#pragma unroll
    for (int i = 0; i < 4; i++)
        t[ty + i*8][tx] = S[(long long)(r0 + ty + i*8) * PN + n0 + tx];
    __syncthreads();
    bf16* DH = dh + b * (long long)R * PN;
    bf16* DL = dl + b * (long long)R * PN;
#pragma unroll
    for (int i = 0; i < 4; i++) {
        float v = t[tx][ty + i*8];
        bf16 h = __float2bfloat16_rn(v);
        long long off = (long long)(n0 + ty + i*8) * R + r0 + tx;
        DH[off] = h;
        DL[off] = __float2bfloat16_rn(v - __bfloat162float(h));
    }
}

// Elementwise hi/lo split (weights): fp32 -> bf16 h/l
__global__ void __launch_bounds__(256)
esplit(const float* __restrict__ src, bf16* __restrict__ dh, bf16* __restrict__ dl, int n)
{
    int i = blockIdx.x * 256 + threadIdx.x;
    if (i < n) {
        float v = src[i];
        bf16 h = __float2bfloat16_rn(v);
        dh[i] = h;
        dl[i] = __float2bfloat16_rn(v - __bfloat162float(h));
    }
}

// ----------------------------------------------------------------------------
// Row softmax (N=4096), IN PLACE, vectorized: float4 loads, warp-shuffle
// reductions, uint2 bf16-packed stores -> [ah (bf16) | al (bf16)] per row.
// ----------------------------------------------------------------------------
__global__ void __launch_bounds__(256)
softmax_split_inplace(float* __restrict__ e)
{
    float* p = e + (size_t)blockIdx.x * PN;
    const int tid = threadIdx.x;
    const int warp = tid >> 5, lane = tid & 31;

    const float4* p4 = (const float4*)p;     // 1024 float4 per row
    float4 v[4];
    float mx = -1e30f;
#pragma unroll
    for (int i = 0; i < 4; i++) {
        v[i] = p4[tid + i * 256];
        mx = fmaxf(mx, fmaxf(fmaxf(v[i].x, v[i].y), fmaxf(v[i].z, v[i].w)));
    }
#pragma unroll
    for (int o = 16; o > 0; o >>= 1) mx = fmaxf(mx, __shfl_xor_sync(0xffffffffu, mx, o));

    __shared__ float red[8];
    if (lane == 0) red[warp] = mx;
    __syncthreads();
#pragma unroll
    for (int i = 0; i < 8; i++) mx = fmaxf(mx, red[i]);
    __syncthreads();

    float sum = 0.0f;
#pragma unroll
    for (int i = 0; i < 4; i++) {
        v[i].x = __expf(v[i].x - mx);
        v[i].y = __expf(v[i].y - mx);
        v[i].z = __expf(v[i].z - mx);
        v[i].w = __expf(v[i].w - mx);
        sum += (v[i].x + v[i].y) + (v[i].z + v[i].w);
    }
#pragma unroll
    for (int o = 16; o > 0; o >>= 1) sum += __shfl_xor_sync(0xffffffffu, sum, o);
    if (lane == 0) red[warp] = sum;
    __syncthreads();
    sum = 0.0f;
#pragma unroll
    for (int i = 0; i < 8; i++) sum += red[i];
    const float inv = 1.0f / sum;

    uint2* ph = (uint2*)p;          // 1024 x (4 bf16) = first 8 KB
    uint2* pl = ph + 1024;          // second 8 KB
#pragma unroll
    for (int i = 0; i < 4; i++) {
        float r0 = v[i].x * inv, r1 = v[i].y * inv, r2 = v[i].z * inv, r3 = v[i].w * inv;
        bf16 h0 = __float2bfloat16_rn(r0), h1 = __float2bfloat16_rn(r1);
        bf16 h2 = __float2bfloat16_rn(r2), h3 = __float2bfloat16_rn(r3);
        __nv_bfloat162 ha; ha.x = h0; ha.y = h1;
        __nv_bfloat162 hb; hb.x = h2; hb.y = h3;
        __nv_bfloat162 la; la.x = __float2bfloat16_rn(r0 - __bfloat162float(h0));
                           la.y = __float2bfloat16_rn(r1 - __bfloat162float(h1));
        __nv_bfloat162 lb; lb.x = __float2bfloat16_rn(r2 - __bfloat162float(h2));
                           lb.y = __float2bfloat16_rn(r3 - __bfloat162float(h3));
        uint2 hu, lu;
        hu.x = *(uint32_t*)&ha; hu.y = *(uint32_t*)&hb;
        lu.x = *(uint32_t*)&la; lu.y = *(uint32_t*)&lb;
        ph[tid + i * 256] = hu;
        pl[tid + i * 256] = lu;
    }
}

// ----------------------------------------------------------------------------
// Launch
// ----------------------------------------------------------------------------
extern "C" void kernel_launch(void* const* d_in, const int* in_sizes, int n_in,
                              void* d_out, int out_size)
{
    (void)in_sizes; (void)n_in; (void)out_size;
    const float* x  = (const float*)d_in[0];
    const float* wq = (const float*)d_in[1];
    const float* bq = (const float*)d_in[2];
    const float* wk = (const float*)d_in[3];
    const float* bk = (const float*)d_in[4];
    const float* wv = (const float*)d_in[5];
    const float* bv = (const float*)d_in[6];
    const float* wo = (const float*)d_in[7];
    const float* bo = (const float*)d_in[8];
    float* out = (float*)d_out;

    static float *e = nullptr;
    static bf16 *xth,*xtl,*qh,*ql,*kh,*kl,*vh,*vl,*oh,*ol;
    static bf16 *wqh,*wql,*wkh,*wkl,*wvh,*wvl,*woh,*wol;
    if (!e) {
        cudaGetSymbolAddress((void**)&e,   g_e);
        cudaGetSymbolAddress((void**)&qh,  g_qh);
        cudaGetSymbolAddress((void**)&ql,  g_ql);
        cudaGetSymbolAddress((void**)&kh,  g_kh);
        cudaGetSymbolAddress((void**)&kl,  g_kl);
        cudaGetSymbolAddress((void**)&vh,  g_vh);
        cudaGetSymbolAddress((void**)&vl,  g_vl);
        cudaGetSymbolAddress((void**)&oh,  g_oh);
        cudaGetSymbolAddress((void**)&ol,  g_ol);
        cudaGetSymbolAddress((void**)&wqh, g_wqh);
        cudaGetSymbolAddress((void**)&wql, g_wql);
        cudaGetSymbolAddress((void**)&wkh, g_wkh);
        cudaGetSymbolAddress((void**)&wkl, g_wkl);
        cudaGetSymbolAddress((void**)&wvh, g_wvh);
        cudaGetSymbolAddress((void**)&wvl, g_wvl);
        cudaGetSymbolAddress((void**)&woh, g_woh);
        cudaGetSymbolAddress((void**)&wol, g_wol);
        // Phase-A aliases inside g_e: xth | xtl (dead before energy GEMM writes g_e)
        xth = (bf16*)e;
        xtl = xth + (size_t)PB * PN * PC;
    }

    const long long N = PN, C = PC, CI = PCI;
    const long long xsb = C * N;          // x / out batch stride
    const long long tsb = N * C;          // xt batch stride [n][c]
    const long long qsb = N * CI;         // q/k/o batch stride [i][ci]
    const long long vsb = CI * N;         // v batch stride [ci][j]
    const long long esb = N * N;
    dim3 blk(256);

    // 0) split x (transposed, into g_e scratch) + weights
    tsplit<<<dim3(PN/32, PC/32, PB), dim3(32,8)>>>(x, xth, xtl, PC);
    esplit<<<PCI*PC/256, blk>>>(wq, wqh, wql, PCI*PC);
    esplit<<<PCI*PC/256, blk>>>(wk, wkh, wkl, PCI*PC);
    esplit<<<PCI*PC/256, blk>>>(wv, wvh, wvl, PCI*PC);
    esplit<<<PC*PCI/256, blk>>>(wo, woh, wol, PC*PCI);

    // 1) q,k: C[i][ci] = sum_c xt[i][c] * wq[ci][c]  (+bq per col) -> bf16 h/l
    mma_gemm3<64,128,32,32,1,2><<<dim3(1, PN/64, PB), blk>>>(
        xth, xtl, tsb, PC,  wqh, wql, 0, PC,
        nullptr, qh, ql, qsb, PCI,  bq, nullptr, 0, PC);
    mma_gemm3<64,128,32,32,1,2><<<dim3(1, PN/64, PB), blk>>>(
        xth, xtl, tsb, PC,  wkh, wkl, 0, PC,
        nullptr, kh, kl, qsb, PCI,  bk, nullptr, 0, PC);

    // 2) v: C[ci][j] = sum_c wv[ci][c] * xt[j][c]  (+bv per row) -> bf16 h/l
    mma_gemm3<64,128,32,32,1,1><<<dim3(PN/128, PCI/64, PB), blk>>>(
        wvh, wvl, 0, PC,  xth, xtl, tsb, PC,
        nullptr, vh, vl, vsb, PN,  bv, nullptr, 0, PC);

    // 3) energy[i][j] = sum_ci q[i][ci] k[j][ci]  -> fp32 (first writer of g_e)
    mma_gemm3<128,128,32,64,0,0><<<dim3(PN/128, PN/128, PB), blk>>>(
        qh, ql, qsb, PCI,  kh, kl, qsb, PCI,
        e, nullptr, nullptr, esb, PN,  nullptr, nullptr, 0, PCI);

    // 4) softmax rows -> attn bf16 h/l packed in place
    softmax_split_inplace<<<PB * PN, blk>>>(e);

    // 5) O[i][ci] = sum_j attn[i][j] v[ci][j]  -> bf16 h/l
    mma_gemm3<64,128,32,32,1,0><<<dim3(1, PN/64, PB), blk>>>(
        (const bf16*)e, (const bf16*)e + PN, 2*esb, 2*PN,
        vh, vl, vsb, PN,
        nullptr, oh, ol, qsb, PCI,  nullptr, nullptr, 0, PN);

    // 6) out[c][n] = sum_ci wo[c][ci] * O[n][ci] + bo + x  -> fp32 d_out
    mma_gemm3<128,128,32,64,0,1><<<dim3(PN/128, PC/128, PB), blk>>>(
        woh, wol, 0, PCI,  oh, ol, qsb, PCI,
        out, nullptr, nullptr, xsb, PN,  bo, x, xsb, PCI);
}

// round 10
// speedup vs baseline: 3.0031x; 1.1084x over previous
#include <cuda_runtime.h>
#include <cuda_bf16.h>
#include <cuda_fp16.h>
#include <cstdint>

// Problem constants: B=4, C=512, CI=128, H=W=64, N=4096
#define PB  4
#define PC  512
#define PCI 128
#define PN  4096

typedef __nv_bfloat16 bf16;

// ---------------- scratch (~309 MB of __device__ globals) -------------------
// g_e: (phase A) xth/xtl transpose-split scratch, then (phase B) fp32 energy
// -> in-place fp16 attn (first 8KB of each 16KB row region).
__device__ float g_e[(size_t)PB * PN * PN];              // 268 MB
__device__ bf16  g_qh[(size_t)PB * PN * PCI];            // [b][i][ci] (bf16 h/l)
__device__ bf16  g_ql[(size_t)PB * PN * PCI];
__device__ bf16  g_kh[(size_t)PB * PN * PCI];
__device__ bf16  g_kl[(size_t)PB * PN * PCI];
__device__ bf16  g_vh[(size_t)PB * PCI * PN];            // [b][ci][j] (fp16 h/l bit patterns)
__device__ bf16  g_vl[(size_t)PB * PCI * PN];
__device__ bf16  g_oh[(size_t)PB * PN * PCI];            // [b][i][ci] (bf16 h/l)
__device__ bf16  g_ol[(size_t)PB * PN * PCI];
__device__ bf16  g_wqh[PCI * PC], g_wql[PCI * PC];
__device__ bf16  g_wkh[PCI * PC], g_wkl[PCI * PC];
__device__ bf16  g_wvh[PCI * PC], g_wvl[PCI * PC];
__device__ bf16  g_woh[PC * PCI], g_wol[PC * PCI];

// ----------------------------------------------------------------------------
// Tensor-core GEMM, hi/lo split:
//   C[b][m][n] = sum_k A[b][m][k] * B[b][n][k]
// OMODE: 0 = fp32 out (+res), 1 = bf16 h/l out, 2 = fp16 h/l out
// BMODE: 0 = none, 1 = bias[m], 2 = bias[n]
// TERMS: 3 = ah*bh + ah*bl + al*bh ; 2 = ah*bh + ah*bl (A single precision)
// F16:   mma dtype f16 (operands are fp16 bit patterns) vs bf16
// ----------------------------------------------------------------------------
template<int BM, int BN, int WM, int WN, int OMODE, int BMODE, int TERMS, bool F16>
__global__ void __launch_bounds__(256)
mma_gemm3(const bf16* __restrict__ Ah, const bf16* __restrict__ Al,
          long long a_bs, int lda,
          const bf16* __restrict__ Bh, const bf16* __restrict__ Bl,
          long long b_bs, int ldb,
          float* __restrict__ C, bf16* __restrict__ Dh, bf16* __restrict__ Dl,
          long long c_bs, int ldc,
          const float* __restrict__ bias,
          const float* __restrict__ res, long long r_sb,
          int K)
{
    constexpr int BK  = 32;
    constexpr int LDS = BK + 8;           // padded row stride; 80 B = 5*16 B
    constexpr int WARPS_M = BM / WM;
    constexpr int MT = WM / 16;
    constexpr int NT = WN / 8;
    constexpr int AV = BM * 8 / 256;
    constexpr int BV = BN * 8 / 256;

    __shared__ bf16 sAh[BM][LDS];
    __shared__ bf16 sAl[(TERMS == 3) ? BM : 1][LDS];
    __shared__ bf16 sBh[BN][LDS], sBl[BN][LDS];

    const int tid  = threadIdx.x;
    const int warp = tid >> 5;
    const int lane = tid & 31;
    const int wm = (warp % WARPS_M) * WM;
    const int wn = (warp / WARPS_M) * WN;

    const long long m0 = (long long)blockIdx.y * BM;
    const long long n0 = (long long)blockIdx.x * BN;
    const bf16* Abh = Ah + blockIdx.z * a_bs + m0 * lda;
    const bf16* Abl = Al + blockIdx.z * a_bs + m0 * lda;
    const bf16* Bbh = Bh + blockIdx.z * b_bs + n0 * ldb;
    const bf16* Bbl = Bl + blockIdx.z * b_bs + n0 * ldb;

    float acc[MT][NT][4];
#pragma unroll
    for (int i = 0; i < MT; i++)
#pragma unroll
        for (int j = 0; j < NT; j++)
#pragma unroll
            for (int r = 0; r < 4; r++) acc[i][j][r] = 0.0f;

    const int a_row = lane & 15, a_kh = (lane >> 4) << 3;
    const int b_row = (lane & 7) + ((lane >> 4) << 3), b_kh = lane & 8;

    // ---- register staging for the software pipeline ----
    uint2 pah[AV], pal[(TERMS == 3) ? AV : 1], pbh[BV], pbl[BV];
    const int ar = tid >> 3;
    const int av = (tid & 7) << 2;

#define PREFETCH(kt_)                                                             \
    {                                                                             \
        _Pragma("unroll")                                                         \
        for (int i = 0; i < AV; i++) {                                            \
            int r = ar + i * 32;                                                  \
            pah[i] = *(const uint2*)&Abh[(long long)r * lda + (kt_) + av];        \
            if (TERMS == 3)                                                       \
                pal[i] = *(const uint2*)&Abl[(long long)r * lda + (kt_) + av];    \
        }                                                                         \
        _Pragma("unroll")                                                         \
        for (int i = 0; i < BV; i++) {                                            \
            int r = ar + i * 32;                                                  \
            pbh[i] = *(const uint2*)&Bbh[(long long)r * ldb + (kt_) + av];        \
            pbl[i] = *(const uint2*)&Bbl[(long long)r * ldb + (kt_) + av];        \
        }                                                                         \
    }

    PREFETCH(0);

    for (int kt = 0; kt < K; kt += BK) {
        // ---- drain staged registers into smem ----
#pragma unroll
        for (int i = 0; i < AV; i++) {
            int r = ar + i * 32;
            *(uint2*)&sAh[r][av] = pah[i];
            if (TERMS == 3) *(uint2*)&sAl[r][av] = pal[i];
        }
#pragma unroll
        for (int i = 0; i < BV; i++) {
            int r = ar + i * 32;
            *(uint2*)&sBh[r][av] = pbh[i];
            *(uint2*)&sBl[r][av] = pbl[i];
        }
        __syncthreads();

        // ---- prefetch next tile (overlaps with mma work below) ----
        if (kt + BK < K) PREFETCH(kt + BK);

#pragma unroll
        for (int ks = 0; ks < 2; ks++) {
            const int kc = ks * 16;
            uint32_t afh[MT][4], afl[MT][4];
#pragma unroll
            for (int mt = 0; mt < MT; mt++) {
                uint32_t ah_ = (uint32_t)__cvta_generic_to_shared(&sAh[wm + mt*16 + a_row][kc + a_kh]);
                asm volatile("ldmatrix.sync.aligned.m8n8.x4.shared.b16 {%0,%1,%2,%3}, [%4];"
                    : "=r"(afh[mt][0]), "=r"(afh[mt][1]), "=r"(afh[mt][2]), "=r"(afh[mt][3]) : "r"(ah_));
                if (TERMS == 3) {
                    uint32_t al_ = (uint32_t)__cvta_generic_to_shared(&sAl[wm + mt*16 + a_row][kc + a_kh]);
                    asm volatile("ldmatrix.sync.aligned.m8n8.x4.shared.b16 {%0,%1,%2,%3}, [%4];"
                        : "=r"(afl[mt][0]), "=r"(afl[mt][1]), "=r"(afl[mt][2]), "=r"(afl[mt][3]) : "r"(al_));
                }
            }
            uint32_t bfh[NT][2], bfl[NT][2];
#pragma unroll
            for (int jt = 0; jt < NT; jt += 2) {
                uint32_t bh_ = (uint32_t)__cvta_generic_to_shared(&sBh[wn + jt*8 + b_row][kc + b_kh]);
                uint32_t bl_ = (uint32_t)__cvta_generic_to_shared(&sBl[wn + jt*8 + b_row][kc + b_kh]);
                asm volatile("ldmatrix.sync.aligned.m8n8.x4.shared.b16 {%0,%1,%2,%3}, [%4];"
                    : "=r"(bfh[jt][0]), "=r"(bfh[jt][1]), "=r"(bfh[jt+1][0]), "=r"(bfh[jt+1][1]) : "r"(bh_));
                asm volatile("ldmatrix.sync.aligned.m8n8.x4.shared.b16 {%0,%1,%2,%3}, [%4];"
                    : "=r"(bfl[jt][0]), "=r"(bfl[jt][1]), "=r"(bfl[jt+1][0]), "=r"(bfl[jt+1][1]) : "r"(bl_));
            }
#pragma unroll
            for (int mt = 0; mt < MT; mt++)
#pragma unroll
                for (int jt = 0; jt < NT; jt++) {
                    float* d = acc[mt][jt];
#define MMA_T(A0,A1,A2,A3,B0,B1)                                                  \
    if (F16)                                                                      \
        asm volatile("mma.sync.aligned.m16n8k16.row.col.f32.f16.f16.f32 "        \
            "{%0,%1,%2,%3}, {%4,%5,%6,%7}, {%8,%9}, {%0,%1,%2,%3};"              \
            : "+f"(d[0]), "+f"(d[1]), "+f"(d[2]), "+f"(d[3])                     \
            : "r"(A0), "r"(A1), "r"(A2), "r"(A3), "r"(B0), "r"(B1));             \
    else                                                                          \
        asm volatile("mma.sync.aligned.m16n8k16.row.col.f32.bf16.bf16.f32 "      \
            "{%0,%1,%2,%3}, {%4,%5,%6,%7}, {%8,%9}, {%0,%1,%2,%3};"              \
            : "+f"(d[0]), "+f"(d[1]), "+f"(d[2]), "+f"(d[3])                     \
            : "r"(A0), "r"(A1), "r"(A2), "r"(A3), "r"(B0), "r"(B1))
                    MMA_T(afh[mt][0], afh[mt][1], afh[mt][2], afh[mt][3], bfh[jt][0], bfh[jt][1]);
                    MMA_T(afh[mt][0], afh[mt][1], afh[mt][2], afh[mt][3], bfl[jt][0], bfl[jt][1]);
                    if (TERMS == 3)
                        MMA_T(afl[mt][0], afl[mt][1], afl[mt][2], afl[mt][3], bfh[jt][0], bfh[jt][1]);
#undef MMA_T
                }
        }
        __syncthreads();
    }
#undef PREFETCH

    // ---- epilogue ----
    const int cr = lane >> 2, cc = (lane & 3) << 1;
    if (OMODE == 0) {
        float* Cb = C + blockIdx.z * c_bs;
        const float* Rb = res ? res + blockIdx.z * r_sb : nullptr;
#pragma unroll
        for (int mt = 0; mt < MT; mt++)
#pragma unroll
            for (int jt = 0; jt < NT; jt++) {
#pragma unroll
                for (int half = 0; half < 2; half++) {
                    long long row = m0 + wm + mt*16 + cr + half*8;
                    long long col = n0 + wn + jt*8 + cc;
                    float v0 = acc[mt][jt][half*2 + 0];
                    float v1 = acc[mt][jt][half*2 + 1];
                    if (BMODE == 1) { float bv = bias[row]; v0 += bv; v1 += bv; }
                    else if (BMODE == 2) { v0 += bias[col]; v1 += bias[col + 1]; }
                    if (Rb) {
                        const float2 rv = *(const float2*)&Rb[row * ldc + col];
                        v0 += rv.x; v1 += rv.y;
                    }
                    *(float2*)&Cb[row * ldc + col] = make_float2(v0, v1);
                }
            }
    } else if (OMODE == 1) {
        bf16* DhB = Dh + blockIdx.z * c_bs;
        bf16* DlB = Dl + blockIdx.z * c_bs;
#pragma unroll
        for (int mt = 0; mt < MT; mt++)
#pragma unroll
            for (int jt = 0; jt < NT; jt++) {
#pragma unroll
                for (int half = 0; half < 2; half++) {
                    long long row = m0 + wm + mt*16 + cr + half*8;
                    long long col = n0 + wn + jt*8 + cc;
                    float v0 = acc[mt][jt][half*2 + 0];
                    float v1 = acc[mt][jt][half*2 + 1];
                    if (BMODE == 1) { float bv = bias[row]; v0 += bv; v1 += bv; }
                    else if (BMODE == 2) { v0 += bias[col]; v1 += bias[col + 1]; }
                    bf16 h0 = __float2bfloat16_rn(v0);
                    bf16 h1 = __float2bfloat16_rn(v1);
                    __nv_bfloat162 hp; hp.x = h0; hp.y = h1;
                    __nv_bfloat162 lp;
                    lp.x = __float2bfloat16_rn(v0 - __bfloat162float(h0));
                    lp.y = __float2bfloat16_rn(v1 - __bfloat162float(h1));
                    *(__nv_bfloat162*)&DhB[row * ldc + col] = hp;
                    *(__nv_bfloat162*)&DlB[row * ldc + col] = lp;
                }
            }
    } else {
        // fp16 h/l output (bit patterns stored in bf16 arrays)
        __half* DhB = (__half*)(Dh + blockIdx.z * c_bs);
        __half* DlB = (__half*)(Dl + blockIdx.z * c_bs);
#pragma unroll
        for (int mt = 0; mt < MT; mt++)
#pragma unroll
            for (int jt = 0; jt < NT; jt++) {
#pragma unroll
                for (int half = 0; half < 2; half++) {
                    long long row = m0 + wm + mt*16 + cr + half*8;
                    long long col = n0 + wn + jt*8 + cc;
                    float v0 = acc[mt][jt][half*2 + 0];
                    float v1 = acc[mt][jt][half*2 + 1];
                    if (BMODE == 1) { float bv = bias[row]; v0 += bv; v1 += bv; }
                    else if (BMODE == 2) { v0 += bias[col]; v1 += bias[col + 1]; }
                    __half h0 = __float2half_rn(v0);
                    __half h1 = __float2half_rn(v1);
                    __half2 hp; hp.x = h0; hp.y = h1;
                    __half2 lp;
                    lp.x = __float2half_rn(v0 - __half2float(h0));
                    lp.y = __float2half_rn(v1 - __half2float(h1));
                    *(__half2*)&DhB[row * ldc + col] = hp;
                    *(__half2*)&DlB[row * ldc + col] = lp;
                }
            }
    }
}

// ----------------------------------------------------------------------------
// Transpose + hi/lo split: src fp32 [b][R][N] -> dh/dl bf16 [b][N][R]
// ----------------------------------------------------------------------------
__global__ void __launch_bounds__(256)
tsplit(const float* __restrict__ src, bf16* __restrict__ dh, bf16* __restrict__ dl, int R)
{
    __shared__ float t[32][33];
    const int tx = threadIdx.x, ty = threadIdx.y;           // 32 x 8
    const long long b = blockIdx.z;
    const int n0 = blockIdx.x * 32, r0 = blockIdx.y * 32;
    const float* S = src + b * (long long)R * PN;
#pragma unroll
    for (int i = 0; i < 4; i++)
        t[ty + i*8][tx] = S[(long long)(r0 + ty + i*8) * PN + n0 + tx];
    __syncthreads();
    bf16* DH = dh + b * (long long)R * PN;
    bf16* DL = dl + b * (long long)R * PN;
#pragma unroll
    for (int i = 0; i < 4; i++) {
        float v = t[tx][ty + i*8];
        bf16 h = __float2bfloat16_rn(v);
        long long off = (long long)(n0 + ty + i*8) * R + r0 + tx;
        DH[off] = h;
        DL[off] = __float2bfloat16_rn(v - __bfloat162float(h));
    }
}

// Elementwise hi/lo split (weights): fp32 -> bf16 h/l
__global__ void __launch_bounds__(256)
esplit(const float* __restrict__ src, bf16* __restrict__ dh, bf16* __restrict__ dl, int n)
{
    int i = blockIdx.x * 256 + threadIdx.x;
    if (i < n) {
        float v = src[i];
        bf16 h = __float2bfloat16_rn(v);
        dh[i] = h;
        dl[i] = __float2bfloat16_rn(v - __bfloat162float(h));
    }
}

// ----------------------------------------------------------------------------
// Row softmax (N=4096), IN PLACE, vectorized: float4 loads, warp-shuffle
// reductions; writes a SINGLE fp16 attn row (first 8 KB of the row region).
// ----------------------------------------------------------------------------
__global__ void __launch_bounds__(256)
softmax_split_inplace(float* __restrict__ e)
{
    float* p = e + (size_t)blockIdx.x * PN;
    const int tid = threadIdx.x;
    const int warp = tid >> 5, lane = tid & 31;

    const float4* p4 = (const float4*)p;     // 1024 float4 per row
    float4 v[4];
    float mx = -1e30f;
#pragma unroll
    for (int i = 0; i < 4; i++) {
        v[i] = p4[tid + i * 256];
        mx = fmaxf(mx, fmaxf(fmaxf(v[i].x, v[i].y), fmaxf(v[i].z, v[i].w)));
    }
#pragma unroll
    for (int o = 16; o > 0; o >>= 1) mx = fmaxf(mx, __shfl_xor_sync(0xffffffffu, mx, o));

    __shared__ float red[8];
    if (lane == 0) red[warp] = mx;
    __syncthreads();
#pragma unroll
    for (int i = 0; i < 8; i++) mx = fmaxf(mx, red[i]);
    __syncthreads();

    float sum = 0.0f;
#pragma unroll
    for (int i = 0; i < 4; i++) {
        v[i].x = __expf(v[i].x - mx);
        v[i].y = __expf(v[i].y - mx);
        v[i].z = __expf(v[i].z - mx);
        v[i].w = __expf(v[i].w - mx);
        sum += (v[i].x + v[i].y) + (v[i].z + v[i].w);
    }
#pragma unroll
    for (int o = 16; o > 0; o >>= 1) sum += __shfl_xor_sync(0xffffffffu, sum, o);
    if (lane == 0) red[warp] = sum;
    __syncthreads();
    sum = 0.0f;
#pragma unroll
    for (int i = 0; i < 8; i++) sum += red[i];
    const float inv = 1.0f / sum;

    uint2* ph = (uint2*)p;          // 1024 x (4 fp16) = first 8 KB
#pragma unroll
    for (int i = 0; i < 4; i++) {
        float r0 = v[i].x * inv, r1 = v[i].y * inv, r2 = v[i].z * inv, r3 = v[i].w * inv;
        __half2 ha; ha.x = __float2half_rn(r0); ha.y = __float2half_rn(r1);
        __half2 hb; hb.x = __float2half_rn(r2); hb.y = __float2half_rn(r3);
        uint2 hu;
        hu.x = *(uint32_t*)&ha; hu.y = *(uint32_t*)&hb;
        ph[tid + i * 256] = hu;
    }
}

// ----------------------------------------------------------------------------
// Launch
// ----------------------------------------------------------------------------
extern "C" void kernel_launch(void* const* d_in, const int* in_sizes, int n_in,
                              void* d_out, int out_size)
{
    (void)in_sizes; (void)n_in; (void)out_size;
    const float* x  = (const float*)d_in[0];
    const float* wq = (const float*)d_in[1];
    const float* bq = (const float*)d_in[2];
    const float* wk = (const float*)d_in[3];
    const float* bk = (const float*)d_in[4];
    const float* wv = (const float*)d_in[5];
    const float* bv = (const float*)d_in[6];
    const float* wo = (const float*)d_in[7];
    const float* bo = (const float*)d_in[8];
    float* out = (float*)d_out;

    static float *e = nullptr;
    static bf16 *xth,*xtl,*qh,*ql,*kh,*kl,*vh,*vl,*oh,*ol;
    static bf16 *wqh,*wql,*wkh,*wkl,*wvh,*wvl,*woh,*wol;
    if (!e) {
        cudaGetSymbolAddress((void**)&e,   g_e);
        cudaGetSymbolAddress((void**)&qh,  g_qh);
        cudaGetSymbolAddress((void**)&ql,  g_ql);
        cudaGetSymbolAddress((void**)&kh,  g_kh);
        cudaGetSymbolAddress((void**)&kl,  g_kl);
        cudaGetSymbolAddress((void**)&vh,  g_vh);
        cudaGetSymbolAddress((void**)&vl,  g_vl);
        cudaGetSymbolAddress((void**)&oh,  g_oh);
        cudaGetSymbolAddress((void**)&ol,  g_ol);
        cudaGetSymbolAddress((void**)&wqh, g_wqh);
        cudaGetSymbolAddress((void**)&wql, g_wql);
        cudaGetSymbolAddress((void**)&wkh, g_wkh);
        cudaGetSymbolAddress((void**)&wkl, g_wkl);
        cudaGetSymbolAddress((void**)&wvh, g_wvh);
        cudaGetSymbolAddress((void**)&wvl, g_wvl);
        cudaGetSymbolAddress((void**)&woh, g_woh);
        cudaGetSymbolAddress((void**)&wol, g_wol);
        // Phase-A aliases inside g_e: xth | xtl (dead before energy GEMM writes g_e)
        xth = (bf16*)e;
        xtl = xth + (size_t)PB * PN * PC;
    }

    const long long N = PN, C = PC, CI = PCI;
    const long long xsb = C * N;          // x / out batch stride
    const long long tsb = N * C;          // xt batch stride [n][c]
    const long long qsb = N * CI;         // q/k/o batch stride [i][ci]
    const long long vsb = CI * N;         // v batch stride [ci][j]
    const long long esb = N * N;
    dim3 blk(256);

    // 0) split x (transposed, into g_e scratch) + weights
    tsplit<<<dim3(PN/32, PC/32, PB), dim3(32,8)>>>(x, xth, xtl, PC);
    esplit<<<PCI*PC/256, blk>>>(wq, wqh, wql, PCI*PC);
    esplit<<<PCI*PC/256, blk>>>(wk, wkh, wkl, PCI*PC);
    esplit<<<PCI*PC/256, blk>>>(wv, wvh, wvl, PCI*PC);
    esplit<<<PC*PCI/256, blk>>>(wo, woh, wol, PC*PCI);

    // 1) q,k: C[i][ci] = sum_c xt[i][c] * wq[ci][c]  (+bq per col) -> bf16 h/l
    mma_gemm3<64,128,32,32,1,2,3,false><<<dim3(1, PN/64, PB), blk>>>(
        xth, xtl, tsb, PC,  wqh, wql, 0, PC,
        nullptr, qh, ql, qsb, PCI,  bq, nullptr, 0, PC);
    mma_gemm3<64,128,32,32,1,2,3,false><<<dim3(1, PN/64, PB), blk>>>(
        xth, xtl, tsb, PC,  wkh, wkl, 0, PC,
        nullptr, kh, kl, qsb, PCI,  bk, nullptr, 0, PC);

    // 2) v: C[ci][j] = sum_c wv[ci][c] * xt[j][c]  (+bv per row) -> FP16 h/l
    mma_gemm3<64,128,32,32,2,1,3,false><<<dim3(PN/128, PCI/64, PB), blk>>>(
        wvh, wvl, 0, PC,  xth, xtl, tsb, PC,
        nullptr, vh, vl, vsb, PN,  bv, nullptr, 0, PC);

    // 3) energy[i][j] = sum_ci q[i][ci] k[j][ci]  -> fp32 (first writer of g_e)
    mma_gemm3<128,128,32,64,0,0,3,false><<<dim3(PN/128, PN/128, PB), blk>>>(
        qh, ql, qsb, PCI,  kh, kl, qsb, PCI,
        e, nullptr, nullptr, esb, PN,  nullptr, nullptr, 0, PCI);

    // 4) softmax rows -> single fp16 attn row, packed in place
    softmax_split_inplace<<<PB * PN, blk>>>(e);

    // 5) O[i][ci] = sum_j attn[i][j] v[ci][j]  -> bf16 h/l  (fp16 mma, 2 terms)
    mma_gemm3<64,128,32,32,1,0,2,true><<<dim3(1, PN/64, PB), blk>>>(
        (const bf16*)e, (const bf16*)e, 2*esb, 2*PN,
        vh, vl, vsb, PN,
        nullptr, oh, ol, qsb, PCI,  nullptr, nullptr, 0, PN);

    // 6) out[c][n] = sum_ci wo[c][ci] * O[n][ci] + bo + x  -> fp32 d_out
    mma_gemm3<128,128,32,64,0,1,3,false><<<dim3(PN/128, PC/128, PB), blk>>>(
        woh, wol, 0, PCI,  oh, ol, qsb, PCI,
        out, nullptr, nullptr, xsb, PN,  bo, x, xsb, PCI);
}

// round 11
// speedup vs baseline: 3.5062x; 1.1675x over previous
#include <cuda_runtime.h>
#include <cuda_bf16.h>
#include <cuda_fp16.h>
#include <cstdint>

// Problem constants: B=4, C=512, CI=128, H=W=64, N=4096
#define PB  4
#define PC  512
#define PCI 128
#define PN  4096

typedef __nv_bfloat16 bf16;

// ---------------- scratch (~309 MB of __device__ globals) -------------------
__device__ __align__(256) float g_e[(size_t)PB * PN * PN];   // 268 MB: xt scratch -> energy -> fp16 attn
__device__ __align__(256) bf16  g_qh[(size_t)PB * PN * PCI]; // [b][i][ci] bf16 h/l
__device__ __align__(256) bf16  g_ql[(size_t)PB * PN * PCI];
__device__ __align__(256) bf16  g_kh[(size_t)PB * PN * PCI];
__device__ __align__(256) bf16  g_kl[(size_t)PB * PN * PCI];
__device__ __align__(256) bf16  g_vh[(size_t)PB * PCI * PN]; // [b][ci][j] fp16 h/l bit patterns
__device__ __align__(256) bf16  g_vl[(size_t)PB * PCI * PN];
__device__ __align__(256) bf16  g_oh[(size_t)PB * PN * PCI]; // [b][i][ci] bf16 h/l
__device__ __align__(256) bf16  g_ol[(size_t)PB * PN * PCI];
__device__ __align__(256) bf16  g_wqh[PCI * PC], g_wql[PCI * PC];
__device__ __align__(256) bf16  g_wkh[PCI * PC], g_wkl[PCI * PC];
__device__ __align__(256) bf16  g_wvh[PCI * PC], g_wvl[PCI * PC];
__device__ __align__(256) bf16  g_woh[PC * PCI], g_wol[PC * PCI];

// ----------------------------------------------------------------------------
// Tensor-core GEMM, hi/lo split, cp.async double-buffered:
//   C[b][m][n] = sum_k A[b][m][k] * B[b][n][k]
// OMODE: 0 = fp32 out (+res), 1 = bf16 h/l out, 2 = fp16 h/l out
// BMODE: 0 = none, 1 = bias[m], 2 = bias[n]
// TERMS: 3 = ah*bh + ah*bl + al*bh ; 2 = ah*bh + ah*bl (A single precision)
// F16:   mma dtype f16 vs bf16
// Dynamic smem: 2 stages x (AROWS + 2*BN) rows x LDS bf16.
// ----------------------------------------------------------------------------
template<int BM, int BN, int WM, int WN, int OMODE, int BMODE, int TERMS, bool F16>
__global__ void __launch_bounds__(256)
mma_gemm3(const bf16* __restrict__ Ah, const bf16* __restrict__ Al,
          long long a_bs, int lda,
          const bf16* __restrict__ Bh, const bf16* __restrict__ Bl,
          long long b_bs, int ldb,
          float* __restrict__ C, bf16* __restrict__ Dh, bf16* __restrict__ Dl,
          long long c_bs, int ldc,
          const float* __restrict__ bias,
          const float* __restrict__ res, long long r_sb,
          int K)
{
    constexpr int BK  = 32;
    constexpr int LDS = 40;               // padded row stride; 80 B = 5*16 B
    constexpr int WARPS_M = BM / WM;
    constexpr int MT = WM / 16;
    constexpr int NT = WN / 8;
    constexpr int AROWS = (TERMS == 3) ? 2 * BM : BM;
    constexpr int SROWS = AROWS + 2 * BN;      // rows per stage
    constexpr int PASSES = SROWS / 64;         // 256 thr, 4 thr/row (16B quads)
    constexpr int STG = SROWS * LDS;           // elems per stage

    extern __shared__ bf16 sm[];

    const int tid  = threadIdx.x;
    const int warp = tid >> 5;
    const int lane = tid & 31;
    const int wm = (warp % WARPS_M) * WM;
    const int wn = (warp / WARPS_M) * WN;

    const long long m0 = (long long)blockIdx.y * BM;
    const long long n0 = (long long)blockIdx.x * BN;
    const bf16* Abh = Ah + blockIdx.z * a_bs + m0 * lda;
    const bf16* Abl = Al + blockIdx.z * a_bs + m0 * lda;
    const bf16* Bbh = Bh + blockIdx.z * b_bs + n0 * ldb;
    const bf16* Bbl = Bl + blockIdx.z * b_bs + n0 * ldb;

    float acc[MT][NT][4];
#pragma unroll
    for (int i = 0; i < MT; i++)
#pragma unroll
        for (int j = 0; j < NT; j++)
#pragma unroll
            for (int r = 0; r < 4; r++) acc[i][j][r] = 0.0f;

    const int a_row = lane & 15, a_kh = (lane >> 4) << 3;
    const int b_row = (lane & 7) + ((lane >> 4) << 3), b_kh = lane & 8;

    // ---- cp.async loader: thread -> (row, 16B quad) ----
    const int lrow = tid >> 2;            // 0..63
    const int lq8  = (tid & 3) << 3;      // quad offset in elems (0,8,16,24)

    auto issue = [&](int stage, int kt) {
#pragma unroll
        for (int p = 0; p < PASSES; p++) {
            int r = lrow + p * 64;
            const bf16* src;
            if (r < BM)                 src = Abh + (long long)r * lda + kt + lq8;
            else if (r < AROWS)         src = Abl + (long long)(r - BM) * lda + kt + lq8;
            else if (r < AROWS + BN)    src = Bbh + (long long)(r - AROWS) * ldb + kt + lq8;
            else                        src = Bbl + (long long)(r - AROWS - BN) * ldb + kt + lq8;
            uint32_t dst = (uint32_t)__cvta_generic_to_shared(&sm[(size_t)stage * STG + r * LDS + lq8]);
            asm volatile("cp.async.cg.shared.global [%0], [%1], 16;" :: "r"(dst), "l"(src));
        }
        asm volatile("cp.async.commit_group;");
    };

    issue(0, 0);
    int cur = 0;

    for (int kt = 0; kt < K; kt += BK) {
        const bool has_next = (kt + BK < K);
        if (has_next) {
            issue(cur ^ 1, kt + BK);
            asm volatile("cp.async.wait_group 1;");
        } else {
            asm volatile("cp.async.wait_group 0;");
        }
        __syncthreads();

        bf16* sAh = sm + (size_t)cur * STG;
        bf16* sAl = sAh + BM * LDS;                 // valid only if TERMS==3
        bf16* sBh = sAh + AROWS * LDS;
        bf16* sBl = sBh + BN * LDS;

#pragma unroll
        for (int ks = 0; ks < 2; ks++) {
            const int kc = ks * 16;
            uint32_t afh[MT][4], afl[MT][4];
#pragma unroll
            for (int mt = 0; mt < MT; mt++) {
                uint32_t ah_ = (uint32_t)__cvta_generic_to_shared(&sAh[(wm + mt*16 + a_row) * LDS + kc + a_kh]);
                asm volatile("ldmatrix.sync.aligned.m8n8.x4.shared.b16 {%0,%1,%2,%3}, [%4];"
                    : "=r"(afh[mt][0]), "=r"(afh[mt][1]), "=r"(afh[mt][2]), "=r"(afh[mt][3]) : "r"(ah_));
                if (TERMS == 3) {
                    uint32_t al_ = (uint32_t)__cvta_generic_to_shared(&sAl[(wm + mt*16 + a_row) * LDS + kc + a_kh]);
                    asm volatile("ldmatrix.sync.aligned.m8n8.x4.shared.b16 {%0,%1,%2,%3}, [%4];"
                        : "=r"(afl[mt][0]), "=r"(afl[mt][1]), "=r"(afl[mt][2]), "=r"(afl[mt][3]) : "r"(al_));
                }
            }
            uint32_t bfh[NT][2], bfl[NT][2];
#pragma unroll
            for (int jt = 0; jt < NT; jt += 2) {
                uint32_t bh_ = (uint32_t)__cvta_generic_to_shared(&sBh[(wn + jt*8 + b_row) * LDS + kc + b_kh]);
                uint32_t bl_ = (uint32_t)__cvta_generic_to_shared(&sBl[(wn + jt*8 + b_row) * LDS + kc + b_kh]);
                asm volatile("ldmatrix.sync.aligned.m8n8.x4.shared.b16 {%0,%1,%2,%3}, [%4];"
                    : "=r"(bfh[jt][0]), "=r"(bfh[jt][1]), "=r"(bfh[jt+1][0]), "=r"(bfh[jt+1][1]) : "r"(bh_));
                asm volatile("ldmatrix.sync.aligned.m8n8.x4.shared.b16 {%0,%1,%2,%3}, [%4];"
                    : "=r"(bfl[jt][0]), "=r"(bfl[jt][1]), "=r"(bfl[jt+1][0]), "=r"(bfl[jt+1][1]) : "r"(bl_));
            }
#pragma unroll
            for (int mt = 0; mt < MT; mt++)
#pragma unroll
                for (int jt = 0; jt < NT; jt++) {
                    float* d = acc[mt][jt];
#define MMA_T(A0,A1,A2,A3,B0,B1)                                                  \
    if (F16)                                                                      \
        asm volatile("mma.sync.aligned.m16n8k16.row.col.f32.f16.f16.f32 "        \
            "{%0,%1,%2,%3}, {%4,%5,%6,%7}, {%8,%9}, {%0,%1,%2,%3};"              \
            : "+f"(d[0]), "+f"(d[1]), "+f"(d[2]), "+f"(d[3])                     \
            : "r"(A0), "r"(A1), "r"(A2), "r"(A3), "r"(B0), "r"(B1));             \
    else                                                                          \
        asm volatile("mma.sync.aligned.m16n8k16.row.col.f32.bf16.bf16.f32 "      \
            "{%0,%1,%2,%3}, {%4,%5,%6,%7}, {%8,%9}, {%0,%1,%2,%3};"              \
            : "+f"(d[0]), "+f"(d[1]), "+f"(d[2]), "+f"(d[3])                     \
            : "r"(A0), "r"(A1), "r"(A2), "r"(A3), "r"(B0), "r"(B1))
                    MMA_T(afh[mt][0], afh[mt][1], afh[mt][2], afh[mt][3], bfh[jt][0], bfh[jt][1]);
                    MMA_T(afh[mt][0], afh[mt][1], afh[mt][2], afh[mt][3], bfl[jt][0], bfl[jt][1]);
                    if (TERMS == 3)
                        MMA_T(afl[mt][0], afl[mt][1], afl[mt][2], afl[mt][3], bfh[jt][0], bfh[jt][1]);
#undef MMA_T
                }
        }
        __syncthreads();
        cur ^= 1;
    }

    // ---- epilogue ----
    const int cr = lane >> 2, cc = (lane & 3) << 1;
    if (OMODE == 0) {
        float* Cb = C + blockIdx.z * c_bs;
        const float* Rb = res ? res + blockIdx.z * r_sb : nullptr;
#pragma unroll
        for (int mt = 0; mt < MT; mt++)
#pragma unroll
            for (int jt = 0; jt < NT; jt++) {
#pragma unroll
                for (int half = 0; half < 2; half++) {
                    long long row = m0 + wm + mt*16 + cr + half*8;
                    long long col = n0 + wn + jt*8 + cc;
                    float v0 = acc[mt][jt][half*2 + 0];
                    float v1 = acc[mt][jt][half*2 + 1];
                    if (BMODE == 1) { float bv = bias[row]; v0 += bv; v1 += bv; }
                    else if (BMODE == 2) { v0 += bias[col]; v1 += bias[col + 1]; }
                    if (Rb) {
                        const float2 rv = *(const float2*)&Rb[row * ldc + col];
                        v0 += rv.x; v1 += rv.y;
                    }
                    *(float2*)&Cb[row * ldc + col] = make_float2(v0, v1);
                }
            }
    } else if (OMODE == 1) {
        bf16* DhB = Dh + blockIdx.z * c_bs;
        bf16* DlB = Dl + blockIdx.z * c_bs;
#pragma unroll
        for (int mt = 0; mt < MT; mt++)
#pragma unroll
            for (int jt = 0; jt < NT; jt++) {
#pragma unroll
                for (int half = 0; half < 2; half++) {
                    long long row = m0 + wm + mt*16 + cr + half*8;
                    long long col = n0 + wn + jt*8 + cc;
                    float v0 = acc[mt][jt][half*2 + 0];
                    float v1 = acc[mt][jt][half*2 + 1];
                    if (BMODE == 1) { float bv = bias[row]; v0 += bv; v1 += bv; }
                    else if (BMODE == 2) { v0 += bias[col]; v1 += bias[col + 1]; }
                    bf16 h0 = __float2bfloat16_rn(v0);
                    bf16 h1 = __float2bfloat16_rn(v1);
                    __nv_bfloat162 hp; hp.x = h0; hp.y = h1;
                    __nv_bfloat162 lp;
                    lp.x = __float2bfloat16_rn(v0 - __bfloat162float(h0));
                    lp.y = __float2bfloat16_rn(v1 - __bfloat162float(h1));
                    *(__nv_bfloat162*)&DhB[row * ldc + col] = hp;
                    *(__nv_bfloat162*)&DlB[row * ldc + col] = lp;
                }
            }
    } else {
        __half* DhB = (__half*)(Dh + blockIdx.z * c_bs);
        __half* DlB = (__half*)(Dl + blockIdx.z * c_bs);
#pragma unroll
        for (int mt = 0; mt < MT; mt++)
#pragma unroll
            for (int jt = 0; jt < NT; jt++) {
#pragma unroll
                for (int half = 0; half < 2; half++) {
                    long long row = m0 + wm + mt*16 + cr + half*8;
                    long long col = n0 + wn + jt*8 + cc;
                    float v0 = acc[mt][jt][half*2 + 0];
                    float v1 = acc[mt][jt][half*2 + 1];
                    if (BMODE == 1) { float bv = bias[row]; v0 += bv; v1 += bv; }
                    else if (BMODE == 2) { v0 += bias[col]; v1 += bias[col + 1]; }
                    __half h0 = __float2half_rn(v0);
                    __half h1 = __float2half_rn(v1);
                    __half2 hp; hp.x = h0; hp.y = h1;
                    __half2 lp;
                    lp.x = __float2half_rn(v0 - __half2float(h0));
                    lp.y = __float2half_rn(v1 - __half2float(h1));
                    *(__half2*)&DhB[row * ldc + col] = hp;
                    *(__half2*)&DlB[row * ldc + col] = lp;
                }
            }
    }
}

// ----------------------------------------------------------------------------
// Transpose + hi/lo split: src fp32 [b][R][N] -> dh/dl bf16 [b][N][R]
// ----------------------------------------------------------------------------
__global__ void __launch_bounds__(256)
tsplit(const float* __restrict__ src, bf16* __restrict__ dh, bf16* __restrict__ dl, int R)
{
    __shared__ float t[32][33];
    const int tx = threadIdx.x, ty = threadIdx.y;           // 32 x 8
    const long long b = blockIdx.z;
    const int n0 = blockIdx.x * 32, r0 = blockIdx.y * 32;
    const float* S = src + b * (long long)R * PN;
#pragma unroll
    for (int i = 0; i < 4; i++)
        t[ty + i*8][tx] = S[(long long)(r0 + ty + i*8) * PN + n0 + tx];
    __syncthreads();
    bf16* DH = dh + b * (long long)R * PN;
    bf16* DL = dl + b * (long long)R * PN;
#pragma unroll
    for (int i = 0; i < 4; i++) {
        float v = t[tx][ty + i*8];
        bf16 h = __float2bfloat16_rn(v);
        long long off = (long long)(n0 + ty + i*8) * R + r0 + tx;
        DH[off] = h;
        DL[off] = __float2bfloat16_rn(v - __bfloat162float(h));
    }
}

// Elementwise hi/lo split (weights): fp32 -> bf16 h/l
__global__ void __launch_bounds__(256)
esplit(const float* __restrict__ src, bf16* __restrict__ dh, bf16* __restrict__ dl, int n)
{
    int i = blockIdx.x * 256 + threadIdx.x;
    if (i < n) {
        float v = src[i];
        bf16 h = __float2bfloat16_rn(v);
        dh[i] = h;
        dl[i] = __float2bfloat16_rn(v - __bfloat162float(h));
    }
}

// ----------------------------------------------------------------------------
// Row softmax (N=4096), IN PLACE, vectorized; writes single fp16 attn row.
// ----------------------------------------------------------------------------
__global__ void __launch_bounds__(256)
softmax_split_inplace(float* __restrict__ e)
{
    float* p = e + (size_t)blockIdx.x * PN;
    const int tid = threadIdx.x;
    const int warp = tid >> 5, lane = tid & 31;

    const float4* p4 = (const float4*)p;
    float4 v[4];
    float mx = -1e30f;
#pragma unroll
    for (int i = 0; i < 4; i++) {
        v[i] = p4[tid + i * 256];
        mx = fmaxf(mx, fmaxf(fmaxf(v[i].x, v[i].y), fmaxf(v[i].z, v[i].w)));
    }
#pragma unroll
    for (int o = 16; o > 0; o >>= 1) mx = fmaxf(mx, __shfl_xor_sync(0xffffffffu, mx, o));

    __shared__ float red[8];
    if (lane == 0) red[warp] = mx;
    __syncthreads();
#pragma unroll
    for (int i = 0; i < 8; i++) mx = fmaxf(mx, red[i]);
    __syncthreads();

    float sum = 0.0f;
#pragma unroll
    for (int i = 0; i < 4; i++) {
        v[i].x = __expf(v[i].x - mx);
        v[i].y = __expf(v[i].y - mx);
        v[i].z = __expf(v[i].z - mx);
        v[i].w = __expf(v[i].w - mx);
        sum += (v[i].x + v[i].y) + (v[i].z + v[i].w);
    }
#pragma unroll
    for (int o = 16; o > 0; o >>= 1) sum += __shfl_xor_sync(0xffffffffu, sum, o);
    if (lane == 0) red[warp] = sum;
    __syncthreads();
    sum = 0.0f;
#pragma unroll
    for (int i = 0; i < 8; i++) sum += red[i];
    const float inv = 1.0f / sum;

    uint2* ph = (uint2*)p;
#pragma unroll
    for (int i = 0; i < 4; i++) {
        float r0 = v[i].x * inv, r1 = v[i].y * inv, r2 = v[i].z * inv, r3 = v[i].w * inv;
        __half2 ha; ha.x = __float2half_rn(r0); ha.y = __float2half_rn(r1);
        __half2 hb; hb.x = __float2half_rn(r2); hb.y = __float2half_rn(r3);
        uint2 hu;
        hu.x = *(uint32_t*)&ha; hu.y = *(uint32_t*)&hb;
        ph[tid + i * 256] = hu;
    }
}

// ----------------------------------------------------------------------------
// Launch
// ----------------------------------------------------------------------------
extern "C" void kernel_launch(void* const* d_in, const int* in_sizes, int n_in,
                              void* d_out, int out_size)
{
    (void)in_sizes; (void)n_in; (void)out_size;
    const float* x  = (const float*)d_in[0];
    const float* wq = (const float*)d_in[1];
    const float* bq = (const float*)d_in[2];
    const float* wk = (const float*)d_in[3];
    const float* bk = (const float*)d_in[4];
    const float* wv = (const float*)d_in[5];
    const float* bv = (const float*)d_in[6];
    const float* wo = (const float*)d_in[7];
    const float* bo = (const float*)d_in[8];
    float* out = (float*)d_out;

    // dynamic smem bytes per instantiation: 2 stages * SROWS * LDS(=40) * 2B
    const int SM_P3  = 2 * (2*64  + 2*128) * 40 * 2;   // 61440 (64x128, TERMS=3)
    const int SM_P2  = 2 * (64    + 2*128) * 40 * 2;   // 51200 (64x128, TERMS=2)
    const int SM_E   = 2 * (2*128 + 2*128) * 40 * 2;   // 81920 (128x128, TERMS=3)

    static float *e = nullptr;
    static bf16 *xth,*xtl,*qh,*ql,*kh,*kl,*vh,*vl,*oh,*ol;
    static bf16 *wqh,*wql,*wkh,*wkl,*wvh,*wvl,*woh,*wol;
    if (!e) {
        cudaGetSymbolAddress((void**)&e,   g_e);
        cudaGetSymbolAddress((void**)&qh,  g_qh);
        cudaGetSymbolAddress((void**)&ql,  g_ql);
        cudaGetSymbolAddress((void**)&kh,  g_kh);
        cudaGetSymbolAddress((void**)&kl,  g_kl);
        cudaGetSymbolAddress((void**)&vh,  g_vh);
        cudaGetSymbolAddress((void**)&vl,  g_vl);
        cudaGetSymbolAddress((void**)&oh,  g_oh);
        cudaGetSymbolAddress((void**)&ol,  g_ol);
        cudaGetSymbolAddress((void**)&wqh, g_wqh);
        cudaGetSymbolAddress((void**)&wql, g_wql);
        cudaGetSymbolAddress((void**)&wkh, g_wkh);
        cudaGetSymbolAddress((void**)&wkl, g_wkl);
        cudaGetSymbolAddress((void**)&wvh, g_wvh);
        cudaGetSymbolAddress((void**)&wvl, g_wvl);
        cudaGetSymbolAddress((void**)&woh, g_woh);
        cudaGetSymbolAddress((void**)&wol, g_wol);
        xth = (bf16*)e;
        xtl = xth + (size_t)PB * PN * PC;
        // opt-in dynamic smem (host-side config; idempotent, done pre-capture)
        cudaFuncSetAttribute(mma_gemm3<64,128,32,32,1,2,3,false>,
                             cudaFuncAttributeMaxDynamicSharedMemorySize, SM_P3);
        cudaFuncSetAttribute(mma_gemm3<64,128,32,32,2,1,3,false>,
                             cudaFuncAttributeMaxDynamicSharedMemorySize, SM_P3);
        cudaFuncSetAttribute(mma_gemm3<128,128,32,64,0,0,3,false>,
                             cudaFuncAttributeMaxDynamicSharedMemorySize, SM_E);
        cudaFuncSetAttribute(mma_gemm3<64,128,32,32,1,0,2,true>,
                             cudaFuncAttributeMaxDynamicSharedMemorySize, SM_P2);
        cudaFuncSetAttribute(mma_gemm3<128,128,32,64,0,1,3,false>,
                             cudaFuncAttributeMaxDynamicSharedMemorySize, SM_E);
    }

    const long long N = PN, C = PC, CI = PCI;
    const long long xsb = C * N;
    const long long tsb = N * C;
    const long long qsb = N * CI;
    const long long vsb = CI * N;
    const long long esb = N * N;
    dim3 blk(256);

    // 0) split x (transposed, into g_e scratch) + weights
    tsplit<<<dim3(PN/32, PC/32, PB), dim3(32,8)>>>(x, xth, xtl, PC);
    esplit<<<PCI*PC/256, blk>>>(wq, wqh, wql, PCI*PC);
    esplit<<<PCI*PC/256, blk>>>(wk, wkh, wkl, PCI*PC);
    esplit<<<PCI*PC/256, blk>>>(wv, wvh, wvl, PCI*PC);
    esplit<<<PC*PCI/256, blk>>>(wo, woh, wol, PC*PCI);

    // 1) q,k: C[i][ci] = sum_c xt[i][c] * wq[ci][c]  (+bq per col) -> bf16 h/l
    mma_gemm3<64,128,32,32,1,2,3,false><<<dim3(1, PN/64, PB), blk, SM_P3>>>(
        xth, xtl, tsb, PC,  wqh, wql, 0, PC,
        nullptr, qh, ql, qsb, PCI,  bq, nullptr, 0, PC);
    mma_gemm3<64,128,32,32,1,2,3,false><<<dim3(1, PN/64, PB), blk, SM_P3>>>(
        xth, xtl, tsb, PC,  wkh, wkl, 0, PC,
        nullptr, kh, kl, qsb, PCI,  bk, nullptr, 0, PC);

    // 2) v: C[ci][j] = sum_c wv[ci][c] * xt[j][c]  (+bv per row) -> FP16 h/l
    mma_gemm3<64,128,32,32,2,1,3,false><<<dim3(PN/128, PCI/64, PB), blk, SM_P3>>>(
        wvh, wvl, 0, PC,  xth, xtl, tsb, PC,
        nullptr, vh, vl, vsb, PN,  bv, nullptr, 0, PC);

    // 3) energy[i][j] = sum_ci q[i][ci] k[j][ci]  -> fp32 (first writer of g_e)
    mma_gemm3<128,128,32,64,0,0,3,false><<<dim3(PN/128, PN/128, PB), blk, SM_E>>>(
        qh, ql, qsb, PCI,  kh, kl, qsb, PCI,
        e, nullptr, nullptr, esb, PN,  nullptr, nullptr, 0, PCI);

    // 4) softmax rows -> single fp16 attn row, packed in place
    softmax_split_inplace<<<PB * PN, blk>>>(e);

    // 5) O[i][ci] = sum_j attn[i][j] v[ci][j]  -> bf16 h/l  (fp16 mma, 2 terms)
    mma_gemm3<64,128,32,32,1,0,2,true><<<dim3(1, PN/64, PB), blk, SM_P2>>>(
        (const bf16*)e, (const bf16*)e, 2*esb, 2*PN,
        vh, vl, vsb, PN,
        nullptr, oh, ol, qsb, PCI,  nullptr, nullptr, 0, PN);

    // 6) out[c][n] = sum_ci wo[c][ci] * O[n][ci] + bo + x  -> fp32 d_out
    mma_gemm3<128,128,32,64,0,1,3,false><<<dim3(PN/128, PC/128, PB), blk, SM_E>>>(
        woh, wol, 0, PCI,  oh, ol, qsb, PCI,
        out, nullptr, nullptr, xsb, PN,  bo, x, xsb, PCI);
}